// round 12
// baseline (speedup 1.0000x reference)
#include <cuda_runtime.h>
#include <cuda_bf16.h>
#include <mma.h>
#include <math.h>
#include <cstdint>

using namespace nvcuda;

#define NNODE 20000
#define NEDGE 400000
#define D_IN  1546
#define D_H   128
#define D_FF  512
#define XSTRIDE 1664   // fp32 X buffer stride

#define KP_IN 1600     // D_IN padded to mult of 64
#define K3_IN (3 * KP_IN)    // 4800
#define K3_H  (3 * D_H)      // 384
#define K3_FF (3 * D_FF)     // 1536
#define NP_LIN 1664    // Wlin'' col stride (13 tiles * 128)

#define BM 128
#define BN 128
#define BK 64
#define APAD (BK + 8)   // 72
#define BPAD (BN + 8)   // 136

// dynamic smem layout (bytes)
#define SM_B_OFF    (2 * BM * APAD * 2)              // 36864
#define SM_BIAS_OFF (SM_B_OFF + 2 * BK * BPAD * 2)   // 71680
#define SM_TOTAL    (SM_BIAS_OFF + 16 * BN * 4)      // 79872

// ---------------- scratch (device globals; no allocations) ----------------
__device__ float g_X [NNODE * XSTRIDE];
__device__ float g_q [NNODE * D_H];
__device__ float g_k [NNODE * D_H];
__device__ float g_v [NNODE * D_H];
__device__ float g_h [NNODE * D_H];
__device__ float g_hi[NNODE * D_H];
__device__ float g_hj[NNODE * D_H];
__device__ float g_ln[NNODE * D_H];
__device__ float g_h2[NNODE * D_H];
__device__ float g_ff[NNODE * D_FF];
__device__ float g_att[NEDGE];
__device__ float g_part[512];
__device__ float g_red[2];

// bf16 split operands (A'' blocks hi,hi,lo ; B'' blocks hi,lo,hi)
__device__ __nv_bfloat16 g_Xs   [(size_t)NNODE * K3_IN];   // 192 MB
__device__ __nv_bfloat16 g_lns  [(size_t)NNODE * K3_H];
__device__ __nv_bfloat16 g_ffs  [(size_t)NNODE * K3_FF];
__device__ __nv_bfloat16 g_W6s  [(size_t)6 * K3_IN * D_H];
__device__ __nv_bfloat16 g_W1s  [(size_t)K3_H * D_FF];
__device__ __nv_bfloat16 g_W2s  [(size_t)K3_FF * D_H];
__device__ __nv_bfloat16 g_Wlins[(size_t)K3_H * NP_LIN];
__device__ __nv_bfloat16 g_Wl2s [(size_t)K3_IN * D_H];

// ---------------- cp.async helpers -----------------------------------------
__device__ __forceinline__ void cp_async16(void* smem_dst, const void* gsrc, bool pred) {
    uint32_t saddr = (uint32_t)__cvta_generic_to_shared(smem_dst);
    int sz = pred ? 16 : 0;
    asm volatile("cp.async.cg.shared.global [%0], [%1], 16, %2;\n"
                 :: "r"(saddr), "l"(gsrc), "r"(sz));
}
__device__ __forceinline__ void cp_commit() { asm volatile("cp.async.commit_group;\n"); }
template <int NREM>
__device__ __forceinline__ void cp_wait() { asm volatile("cp.async.wait_group %0;\n" :: "n"(NREM)); }

// ---------------- split kernels ---------------------------------------------
// A'' (M x 3Kp): stacked hi@0, hi@Kp, lo@2Kp
__global__ __launch_bounds__(256) void splitA_kernel(
    const float* __restrict__ in, int lda, int M, int K, int Kp,
    __nv_bfloat16* __restrict__ out)
{
    int idx = blockIdx.x * 256 + threadIdx.x;
    int total = M * Kp;
    if (idx >= total) return;
    int r = idx / Kp, c = idx - r * Kp;
    float v = (c < K) ? in[(size_t)r * lda + c] : 0.f;
    __nv_bfloat16 hi = __float2bfloat16(v);
    __nv_bfloat16 lo = __float2bfloat16(v - __bfloat162float(hi));
    size_t base = (size_t)r * (3 * Kp);
    out[base + c]          = hi;
    out[base + Kp + c]     = hi;
    out[base + 2 * Kp + c] = lo;
}

// B'' (3Kp x NP): block rows hi, lo, hi -> stacked product = hi*hi + hi*lo + lo*hi
__global__ __launch_bounds__(256) void splitB_kernel(
    const float* __restrict__ in, int K, int N, int Kp, int NP,
    __nv_bfloat16* __restrict__ out)
{
    int idx = blockIdx.x * 256 + threadIdx.x;
    int total = Kp * NP;
    if (idx >= total) return;
    int r = idx / NP, c = idx - r * NP;
    float v = (r < K && c < N) ? in[(size_t)r * N + c] : 0.f;
    __nv_bfloat16 hi = __float2bfloat16(v);
    __nv_bfloat16 lo = __float2bfloat16(v - __bfloat162float(hi));
    out[(size_t)r * NP + c]            = hi;
    out[(size_t)(Kp + r) * NP + c]     = lo;
    out[(size_t)(2 * Kp + r) * NP + c] = hi;
}

// ---------------- bf16 tensor-core GEMM (BK=64, 2-stage cp.async) ----------
template <int ACT>  // 0=none, 1=relu, 2=leaky(0.01)
__device__ __forceinline__ void bgemm_body(
    const __nv_bfloat16* __restrict__ A, int lda,
    const __nv_bfloat16* __restrict__ B, int ldb,
    const float* __restrict__ bias, const float* __restrict__ resid, int ldr,
    float* __restrict__ C, int ldc, int M, int N, int Kt,
    int rowBase, int colBase)
{
    extern __shared__ char smraw[];
    __nv_bfloat16 (*As)[BM][APAD] = reinterpret_cast<__nv_bfloat16 (*)[BM][APAD]>(smraw);
    __nv_bfloat16 (*Bs)[BK][BPAD] = reinterpret_cast<__nv_bfloat16 (*)[BK][BPAD]>(smraw + SM_B_OFF);
    float (*BiasT)[BN] = reinterpret_cast<float (*)[BN]>(smraw + SM_BIAS_OFF);

    const int tid = threadIdx.x;
    const int wid = tid >> 5;
    const int wm  = wid >> 1;
    const int wn  = wid & 1;

    wmma::fragment<wmma::accumulator, 16, 16, 16, float> acc[2][4];
#pragma unroll
    for (int mi = 0; mi < 2; mi++)
#pragma unroll
        for (int ni = 0; ni < 4; ni++) wmma::fill_fragment(acc[mi][ni], 0.f);

    for (int l = tid; l < 16 * BN; l += 256) {
        int r = l >> 7, c = l & 127;
        int gc = colBase + c;
        BiasT[r][c] = (bias != nullptr && gc < N) ? bias[gc] : 0.f;
    }

    const int nK = Kt / BK;

    {   // prologue: stage 0
#pragma unroll
        for (int u = 0; u < 4; u++) {
            int ch = tid + u * 256;
            int r = ch >> 3, c8 = (ch & 7) * 8;
            int gr = rowBase + r;
            cp_async16(&As[0][r][c8], A + (size_t)gr * lda + c8, gr < M);
        }
#pragma unroll
        for (int u = 0; u < 4; u++) {
            int ch = tid + u * 256;
            int r = ch >> 4, c8 = (ch & 15) * 8;
            cp_async16(&Bs[0][r][c8], B + (size_t)r * ldb + colBase + c8, true);
        }
        cp_commit();
    }

    for (int kt = 0; kt < nK; kt++) {
        int cur = kt & 1;
        if (kt + 1 < nK) {
            int nxt = cur ^ 1, k0 = (kt + 1) * BK;
#pragma unroll
            for (int u = 0; u < 4; u++) {
                int ch = tid + u * 256;
                int r = ch >> 3, c8 = (ch & 7) * 8;
                int gr = rowBase + r;
                cp_async16(&As[nxt][r][c8], A + (size_t)gr * lda + k0 + c8, gr < M);
            }
#pragma unroll
            for (int u = 0; u < 4; u++) {
                int ch = tid + u * 256;
                int r = ch >> 4, c8 = (ch & 15) * 8;
                cp_async16(&Bs[nxt][r][c8], B + (size_t)(k0 + r) * ldb + colBase + c8, true);
            }
            cp_commit();
            cp_wait<1>();
        } else {
            cp_wait<0>();
        }
        __syncthreads();

#pragma unroll
        for (int ks = 0; ks < BK; ks += 16) {
            wmma::fragment<wmma::matrix_a, 16, 16, 16, __nv_bfloat16, wmma::row_major> af[2];
            wmma::fragment<wmma::matrix_b, 16, 16, 16, __nv_bfloat16, wmma::row_major> bf[4];
#pragma unroll
            for (int mi = 0; mi < 2; mi++)
                wmma::load_matrix_sync(af[mi], &As[cur][wm * 32 + mi * 16][ks], APAD);
#pragma unroll
            for (int ni = 0; ni < 4; ni++)
                wmma::load_matrix_sync(bf[ni], &Bs[cur][ks][wn * 64 + ni * 16], BPAD);
#pragma unroll
            for (int mi = 0; mi < 2; mi++)
#pragma unroll
                for (int ni = 0; ni < 4; ni++)
                    wmma::mma_sync(acc[mi][ni], af[mi], bf[ni], acc[mi][ni]);
        }
        __syncthreads();
    }

#pragma unroll
    for (int mi = 0; mi < 2; mi++) {
        int grow = rowBase + wm * 32 + mi * 16;
        if (grow >= M) continue;
#pragma unroll
        for (int ni = 0; ni < 4; ni++) {
            int gcol = colBase + wn * 64 + ni * 16;
            wmma::fragment<wmma::accumulator, 16, 16, 16, float> bfr;
            wmma::load_matrix_sync(bfr, &BiasT[0][wn * 64 + ni * 16], BN, wmma::mem_row_major);
            if (resid != nullptr) {
                wmma::fragment<wmma::accumulator, 16, 16, 16, float> rfr;
                wmma::load_matrix_sync(rfr, resid + (size_t)grow * ldr + gcol, ldr,
                                       wmma::mem_row_major);
#pragma unroll
                for (int i = 0; i < acc[mi][ni].num_elements; i++)
                    acc[mi][ni].x[i] += rfr.x[i];
            }
#pragma unroll
            for (int i = 0; i < acc[mi][ni].num_elements; i++) {
                float v = acc[mi][ni].x[i] + bfr.x[i];
                if (ACT == 1) v = fmaxf(v, 0.f);
                if (ACT == 2) v = (v > 0.f) ? v : 0.01f * v;
                acc[mi][ni].x[i] = v;
            }
            wmma::store_matrix_sync(C + (size_t)grow * ldc + gcol, acc[mi][ni], ldc,
                                    wmma::mem_row_major);
        }
    }
}

template <int ACT>
__global__ __launch_bounds__(256) void bgemm_kernel(
    const __nv_bfloat16* __restrict__ A, int lda,
    const __nv_bfloat16* __restrict__ B, int ldb,
    const float* bias, const float* resid, int ldr,
    float* C, int ldc, int M, int N, int Kt)
{
    bgemm_body<ACT>(A, lda, B, ldb, bias, resid, ldr, C, ldc, M, N, Kt,
                    blockIdx.x * BM, blockIdx.y * BN);
}

struct X6Args {
    const __nv_bfloat16* B[6];
    const float* bias[6];
    float*       C[6];
};
// grid (6, rowTiles): projections of the same row tile are adjacent -> A row
// tile is fetched from DRAM once and L2-hit by the other 5 CTAs.
__global__ __launch_bounds__(256) void bgemm_x6_kernel(
    const __nv_bfloat16* __restrict__ A, X6Args p, int M)
{
    int z = blockIdx.x;
    bgemm_body<0>(A, K3_IN, p.B[z], D_H, p.bias[z], nullptr, 0,
                  p.C[z], D_H, M, D_H, K3_IN, blockIdx.y * BM, 0);
}

// ---------------- LayerNorm over 128, warp per row -------------------------
__global__ __launch_bounds__(256) void ln128_kernel(
    const float* __restrict__ in, const float* __restrict__ gamma,
    const float* __restrict__ beta, float* __restrict__ out, int M)
{
    int row = blockIdx.x * 8 + (threadIdx.x >> 5);
    if (row >= M) return;
    int lane = threadIdx.x & 31;
    const float* p = in + (size_t)row * D_H;
    float v0 = p[lane], v1 = p[lane + 32], v2 = p[lane + 64], v3 = p[lane + 96];
    float s = v0 + v1 + v2 + v3;
#pragma unroll
    for (int o = 16; o > 0; o >>= 1) s += __shfl_xor_sync(0xFFFFFFFFu, s, o);
    float mean = s * (1.f / 128.f);
    float d0 = v0 - mean, d1 = v1 - mean, d2 = v2 - mean, d3 = v3 - mean;
    float ss = d0 * d0 + d1 * d1 + d2 * d2 + d3 * d3;
#pragma unroll
    for (int o = 16; o > 0; o >>= 1) ss += __shfl_xor_sync(0xFFFFFFFFu, ss, o);
    float inv = rsqrtf(ss * (1.f / 128.f) + 1e-5f);
    float* q = out + (size_t)row * D_H;
    q[lane]      = d0 * inv * gamma[lane]      + beta[lane];
    q[lane + 32] = d1 * inv * gamma[lane + 32] + beta[lane + 32];
    q[lane + 64] = d2 * inv * gamma[lane + 64] + beta[lane + 64];
    q[lane + 96] = d3 * inv * gamma[lane + 96] + beta[lane + 96];
}

// ---------------- edge kernels (warp per edge; edge_index is int32) --------
__global__ __launch_bounds__(256) void att_dot_kernel(
    const int* __restrict__ ei, const float* __restrict__ q,
    const float* __restrict__ k, float* __restrict__ att, int E)
{
    int e = (blockIdx.x * blockDim.x + threadIdx.x) >> 5;
    if (e >= E) return;
    int lane = threadIdx.x & 31;
    size_t s = (size_t)ei[e];
    size_t d = (size_t)ei[E + e];
    const float* qp = q + d * D_H;
    const float* kp = k + s * D_H;
    float sum = qp[lane] * kp[lane] + qp[lane + 32] * kp[lane + 32] +
                qp[lane + 64] * kp[lane + 64] + qp[lane + 96] * kp[lane + 96];
#pragma unroll
    for (int o = 16; o > 0; o >>= 1) sum += __shfl_xor_sync(0xFFFFFFFFu, sum, o);
    if (lane == 0) att[e] = sum;
}

__global__ __launch_bounds__(256) void reduce_max_p1(
    const float* __restrict__ att, int E, float* __restrict__ part)
{
    __shared__ float sm[256];
    float m = -INFINITY;
    for (int i = blockIdx.x * 256 + threadIdx.x; i < E; i += gridDim.x * 256)
        m = fmaxf(m, att[i]);
    sm[threadIdx.x] = m;
    __syncthreads();
    for (int o = 128; o > 0; o >>= 1) {
        if (threadIdx.x < o) sm[threadIdx.x] = fmaxf(sm[threadIdx.x], sm[threadIdx.x + o]);
        __syncthreads();
    }
    if (threadIdx.x == 0) part[blockIdx.x] = sm[0];
}

__global__ __launch_bounds__(512) void reduce_max_p2(
    const float* __restrict__ part, float* __restrict__ out)
{
    __shared__ float sm[512];
    sm[threadIdx.x] = part[threadIdx.x];
    __syncthreads();
    for (int o = 256; o > 0; o >>= 1) {
        if (threadIdx.x < o) sm[threadIdx.x] = fmaxf(sm[threadIdx.x], sm[threadIdx.x + o]);
        __syncthreads();
    }
    if (threadIdx.x == 0) out[0] = sm[0];
}

__global__ __launch_bounds__(256) void reduce_sum_p1(
    const float* __restrict__ att, const float* __restrict__ maxp,
    int E, float* __restrict__ part)
{
    __shared__ float sm[256];
    float mx = maxp[0];
    float s = 0.f;
    for (int i = blockIdx.x * 256 + threadIdx.x; i < E; i += gridDim.x * 256)
        s += __expf(att[i] - mx);
    sm[threadIdx.x] = s;
    __syncthreads();
    for (int o = 128; o > 0; o >>= 1) {
        if (threadIdx.x < o) sm[threadIdx.x] += sm[threadIdx.x + o];
        __syncthreads();
    }
    if (threadIdx.x == 0) part[blockIdx.x] = sm[0];
}

__global__ __launch_bounds__(512) void reduce_sum_p2(
    const float* __restrict__ part, float* __restrict__ out)
{
    __shared__ float sm[512];
    sm[threadIdx.x] = part[threadIdx.x];
    __syncthreads();
    for (int o = 256; o > 0; o >>= 1) {
        if (threadIdx.x < o) sm[threadIdx.x] += sm[threadIdx.x + o];
        __syncthreads();
    }
    if (threadIdx.x == 0) out[0] = sm[0];
}

__global__ __launch_bounds__(256) void message_kernel(
    const int* __restrict__ ei, const float* __restrict__ ea,
    const float* __restrict__ v, const float* __restrict__ hi,
    const float* __restrict__ hj, const float* __restrict__ att,
    const float* __restrict__ red, float* __restrict__ h, int E)
{
    int e = (blockIdx.x * blockDim.x + threadIdx.x) >> 5;
    if (e >= E) return;
    int lane = threadIdx.x & 31;
    size_t s = (size_t)ei[e];
    size_t d = (size_t)ei[E + e];
    float attn = __expf(att[e] - red[0]) * (1.f / red[1]);
    const float* eap = ea + (size_t)e * D_H;
    const float* vp  = v  + s * D_H;
    const float* hip = hi + s * D_H;
    const float* hjp = hj + d * D_H;
    float* hp = h + d * D_H;
#pragma unroll
    for (int c = 0; c < 4; c++) {
        int dim = lane + c * 32;
        float z = eap[dim] + hip[dim] + hjp[dim];
        float gate = 1.f / (1.f + __expf(-z));
        atomicAdd(&hp[dim], attn * vp[dim] * gate);
    }
}

// ---------------- launch ----------------------------------------------------
static inline int cdiv(int a, int b) { return (a + b - 1) / b; }

extern "C" void kernel_launch(void* const* d_in, const int* in_sizes, int n_in,
                              void* d_out, int out_size)
{
    const float* x    = (const float*)d_in[0];
    const int*   ei   = (const int*)d_in[1];
    const float* ea   = (const float*)d_in[2];
    const float* Wq   = (const float*)d_in[3];
    const float* bq   = (const float*)d_in[4];
    const float* Wk   = (const float*)d_in[5];
    const float* bk   = (const float*)d_in[6];
    const float* Wv   = (const float*)d_in[7];
    const float* bv   = (const float*)d_in[8];
    const float* Wr   = (const float*)d_in[9];
    const float* br   = (const float*)d_in[10];
    const float* Whi  = (const float*)d_in[11];
    const float* Whj  = (const float*)d_in[12];
    const float* g1   = (const float*)d_in[13];
    const float* be1  = (const float*)d_in[14];
    const float* W1   = (const float*)d_in[15];
    const float* bl1  = (const float*)d_in[16];
    const float* W2   = (const float*)d_in[17];
    const float* bl2  = (const float*)d_in[18];
    const float* g2   = (const float*)d_in[19];
    const float* be2  = (const float*)d_in[20];
    const float* Wlin = (const float*)d_in[21];
    const float* blin = (const float*)d_in[22];
    const float* Wlin2= (const float*)d_in[23];
    const float* blin2= (const float*)d_in[24];
    float* out = (float*)d_out;

    float *X, *q, *k, *v, *h, *hi, *hj, *ln, *h2, *ff, *att, *part, *red;
    __nv_bfloat16 *Xs, *lns, *ffs, *W6s, *W1s, *W2s, *Wlins, *Wl2s;
    cudaGetSymbolAddress((void**)&X,   g_X);
    cudaGetSymbolAddress((void**)&q,   g_q);
    cudaGetSymbolAddress((void**)&k,   g_k);
    cudaGetSymbolAddress((void**)&v,   g_v);
    cudaGetSymbolAddress((void**)&h,   g_h);
    cudaGetSymbolAddress((void**)&hi,  g_hi);
    cudaGetSymbolAddress((void**)&hj,  g_hj);
    cudaGetSymbolAddress((void**)&ln,  g_ln);
    cudaGetSymbolAddress((void**)&h2,  g_h2);
    cudaGetSymbolAddress((void**)&ff,  g_ff);
    cudaGetSymbolAddress((void**)&att, g_att);
    cudaGetSymbolAddress((void**)&part,g_part);
    cudaGetSymbolAddress((void**)&red, g_red);
    cudaGetSymbolAddress((void**)&Xs,  g_Xs);
    cudaGetSymbolAddress((void**)&lns, g_lns);
    cudaGetSymbolAddress((void**)&ffs, g_ffs);
    cudaGetSymbolAddress((void**)&W6s, g_W6s);
    cudaGetSymbolAddress((void**)&W1s, g_W1s);
    cudaGetSymbolAddress((void**)&W2s, g_W2s);
    cudaGetSymbolAddress((void**)&Wlins, g_Wlins);
    cudaGetSymbolAddress((void**)&Wl2s,  g_Wl2s);

    // opt-in to 80KB dynamic smem for the GEMM kernels
    cudaFuncSetAttribute(bgemm_kernel<0>, cudaFuncAttributeMaxDynamicSharedMemorySize, SM_TOTAL);
    cudaFuncSetAttribute(bgemm_kernel<1>, cudaFuncAttributeMaxDynamicSharedMemorySize, SM_TOTAL);
    cudaFuncSetAttribute(bgemm_kernel<2>, cudaFuncAttributeMaxDynamicSharedMemorySize, SM_TOTAL);
    cudaFuncSetAttribute(bgemm_x6_kernel, cudaFuncAttributeMaxDynamicSharedMemorySize, SM_TOTAL);

    const int M = NNODE, E = NEDGE;
    const int rowTiles = cdiv(M, BM);
    const int edgeBlocks = (E * 32 + 255) / 256;
    const int lnBlocks = (M + 7) / 8;

    // shared weights: split once
    splitB_kernel<<<cdiv(D_H * NP_LIN, 256), 256>>>(Wlin,  D_H,  D_IN, D_H,  NP_LIN, Wlins);
    splitB_kernel<<<cdiv(KP_IN * D_H, 256), 256>>>(Wlin2, D_IN, D_H,  KP_IN, D_H,   Wl2s);

    const float* xin = x;
    int lda = D_IN;
    for (int i = 0; i < 2; i++) {
        splitA_kernel<<<cdiv(M * KP_IN, 256), 256>>>(xin, lda, M, D_IN, KP_IN, Xs);
        const float* Wp[6] = { Wq + (size_t)i * D_IN * D_H, Wk + (size_t)i * D_IN * D_H,
                               Wv + (size_t)i * D_IN * D_H, Wr + (size_t)i * D_IN * D_H,
                               Whi + (size_t)i * D_IN * D_H, Whj + (size_t)i * D_IN * D_H };
        for (int z = 0; z < 6; z++)
            splitB_kernel<<<cdiv(KP_IN * D_H, 256), 256>>>(
                Wp[z], D_IN, D_H, KP_IN, D_H, W6s + (size_t)z * K3_IN * D_H);

        // 1) fused 6-way projection (grid: 6 x rowTiles for L2 A reuse)
        X6Args a;
        for (int z = 0; z < 6; z++) a.B[z] = W6s + (size_t)z * K3_IN * D_H;
        a.bias[0] = bq + (size_t)i * D_H;  a.C[0] = q;
        a.bias[1] = bk + (size_t)i * D_H;  a.C[1] = k;
        a.bias[2] = bv + (size_t)i * D_H;  a.C[2] = v;
        a.bias[3] = br + (size_t)i * D_H;  a.C[3] = h;
        a.bias[4] = nullptr;               a.C[4] = hi;
        a.bias[5] = nullptr;               a.C[5] = hj;
        bgemm_x6_kernel<<<dim3(6, rowTiles), 256, SM_TOTAL>>>(Xs, a, M);

        // 2) attention + global softmax stats
        att_dot_kernel<<<edgeBlocks, 256>>>(ei, q, k, att, E);
        reduce_max_p1<<<512, 256>>>(att, E, part);
        reduce_max_p2<<<1, 512>>>(part, red);
        reduce_sum_p1<<<512, 256>>>(att, red, E, part);
        reduce_sum_p2<<<1, 512>>>(part, red + 1);

        // 3) gated messages scatter-added onto h
        message_kernel<<<edgeBlocks, 256>>>(ei, ea, v, hi, hj, att, red, h, E);

        // 4) FF MLP with pre-norm residual
        ln128_kernel<<<lnBlocks, 256>>>(h, g1 + (size_t)i * D_H, be1 + (size_t)i * D_H, ln, M);
        splitA_kernel<<<cdiv(M * D_H, 256), 256>>>(ln, D_H, M, D_H, D_H, lns);
        splitB_kernel<<<cdiv(D_H * D_FF, 256), 256>>>(
            W1 + (size_t)i * D_H * D_FF, D_H, D_FF, D_H, D_FF, W1s);
        bgemm_kernel<1><<<dim3(rowTiles, D_FF / BN), 256, SM_TOTAL>>>(
            lns, K3_H, W1s, D_FF, bl1 + (size_t)i * D_FF, nullptr, 0,
            ff, D_FF, M, D_FF, K3_H);
        splitA_kernel<<<cdiv(M * D_FF, 256), 256>>>(ff, D_FF, M, D_FF, D_FF, ffs);
        splitB_kernel<<<cdiv(D_FF * D_H, 256), 256>>>(
            W2 + (size_t)i * D_FF * D_H, D_FF, D_H, D_FF, D_H, W2s);
        bgemm_kernel<0><<<dim3(rowTiles, 1), 256, SM_TOTAL>>>(
            ffs, K3_FF, W2s, D_H, bl2 + (size_t)i * D_H, h, D_H,
            h2, D_H, M, D_H, K3_FF);
        ln128_kernel<<<lnBlocks, 256>>>(h2, g2 + (size_t)i * D_H, be2 + (size_t)i * D_H, ln, M);

        // 5) expand back to 1546 (into padded-stride fp32 X)
        splitA_kernel<<<cdiv(M * D_H, 256), 256>>>(ln, D_H, M, D_H, D_H, lns);
        bgemm_kernel<0><<<dim3(rowTiles, NP_LIN / BN), 256, SM_TOTAL>>>(
            lns, K3_H, Wlins, NP_LIN, blin, nullptr, 0,
            X, XSTRIDE, M, D_IN, K3_H);
        xin = X;
        lda = XSTRIDE;
    }

    // final: leaky_relu(X @ Wlin2 + blin2)
    splitA_kernel<<<cdiv(M * KP_IN, 256), 256>>>(X, XSTRIDE, M, D_IN, KP_IN, Xs);
    bgemm_kernel<2><<<dim3(rowTiles, 1), 256, SM_TOTAL>>>(
        Xs, K3_IN, Wl2s, D_H, blin2, nullptr, 0,
        out, D_H, M, D_H, K3_IN);
}

// round 13
// speedup vs baseline: 1.4076x; 1.4076x over previous
#include <cuda_runtime.h>
#include <cuda_bf16.h>
#include <mma.h>
#include <math.h>
#include <cstdint>

using namespace nvcuda;

#define NNODE 20000
#define NEDGE 400000
#define D_IN  1546
#define D_H   128
#define D_FF  512
#define XSTRIDE 1664   // fp32 X buffer stride

#define KP_IN 1568     // D_IN padded to mult of 32
#define K3_IN (3 * KP_IN)    // 4704
#define K3_H  (3 * D_H)      // 384
#define K3_FF (3 * D_FF)     // 1536
#define NP_LIN 1664    // Wlin'' col stride (13 tiles * 128)

#define BM 128
#define BN 128
#define BK 32

// ---------------- scratch (device globals; no allocations) ----------------
__device__ float g_X [NNODE * XSTRIDE];
__device__ float g_q [NNODE * D_H];
__device__ float g_k [NNODE * D_H];
__device__ float g_v [NNODE * D_H];
__device__ float g_h [NNODE * D_H];
__device__ float g_hi[NNODE * D_H];
__device__ float g_hj[NNODE * D_H];
__device__ float g_ln[NNODE * D_H];
__device__ float g_h2[NNODE * D_H];
__device__ float g_ff[NNODE * D_FF];
__device__ float g_att[NEDGE];
__device__ float g_part[512];
__device__ float g_red[2];

// bf16 split operands (A'' blocks hi,hi,lo ; B'' blocks hi,lo,hi)
__device__ __nv_bfloat16 g_Xs   [(size_t)NNODE * K3_IN];   // 188 MB
__device__ __nv_bfloat16 g_lns  [(size_t)NNODE * K3_H];
__device__ __nv_bfloat16 g_ffs  [(size_t)NNODE * K3_FF];
__device__ __nv_bfloat16 g_W6s  [(size_t)6 * K3_IN * D_H];
__device__ __nv_bfloat16 g_W1s  [(size_t)K3_H * D_FF];
__device__ __nv_bfloat16 g_W2s  [(size_t)K3_FF * D_H];
__device__ __nv_bfloat16 g_Wlins[(size_t)K3_H * NP_LIN];
__device__ __nv_bfloat16 g_Wl2s [(size_t)K3_IN * D_H];

// ---------------- cp.async helpers -----------------------------------------
__device__ __forceinline__ void cp_async16(void* smem_dst, const void* gsrc, bool pred) {
    uint32_t saddr = (uint32_t)__cvta_generic_to_shared(smem_dst);
    int sz = pred ? 16 : 0;
    asm volatile("cp.async.cg.shared.global [%0], [%1], 16, %2;\n"
                 :: "r"(saddr), "l"(gsrc), "r"(sz));
}
__device__ __forceinline__ void cp_commit() { asm volatile("cp.async.commit_group;\n"); }
template <int NREM>
__device__ __forceinline__ void cp_wait() { asm volatile("cp.async.wait_group %0;\n" :: "n"(NREM)); }

// ---------------- split kernels ---------------------------------------------
// A'' (M x 3Kp): stacked hi@0, hi@Kp, lo@2Kp
__global__ __launch_bounds__(256) void splitA_kernel(
    const float* __restrict__ in, int lda, int M, int K, int Kp,
    __nv_bfloat16* __restrict__ out)
{
    int idx = blockIdx.x * 256 + threadIdx.x;
    int total = M * Kp;
    if (idx >= total) return;
    int r = idx / Kp, c = idx - r * Kp;
    float v = (c < K) ? in[(size_t)r * lda + c] : 0.f;
    __nv_bfloat16 hi = __float2bfloat16(v);
    __nv_bfloat16 lo = __float2bfloat16(v - __bfloat162float(hi));
    size_t base = (size_t)r * (3 * Kp);
    out[base + c]          = hi;
    out[base + Kp + c]     = hi;
    out[base + 2 * Kp + c] = lo;
}

// B'' (3Kp x NP): block rows hi, lo, hi -> stacked product = hi*hi + hi*lo + lo*hi
__global__ __launch_bounds__(256) void splitB_kernel(
    const float* __restrict__ in, int K, int N, int Kp, int NP,
    __nv_bfloat16* __restrict__ out)
{
    int idx = blockIdx.x * 256 + threadIdx.x;
    int total = Kp * NP;
    if (idx >= total) return;
    int r = idx / NP, c = idx - r * NP;
    float v = (r < K && c < N) ? in[(size_t)r * N + c] : 0.f;
    __nv_bfloat16 hi = __float2bfloat16(v);
    __nv_bfloat16 lo = __float2bfloat16(v - __bfloat162float(hi));
    out[(size_t)r * NP + c]            = hi;
    out[(size_t)(Kp + r) * NP + c]     = lo;
    out[(size_t)(2 * Kp + r) * NP + c] = hi;
}

// ---------------- bf16 tensor-core GEMM (BK=32, 2-stage cp.async) ----------
// C = act(A''*B'' + bias + resid). A'': M x Kt bf16 (stride lda), B'': Kt x NP
// bf16 (stride ldb, fully padded so no col guard). C fp32 stride ldc.
template <int ACT>  // 0=none, 1=relu, 2=leaky(0.01)
__device__ __forceinline__ void bgemm_body(
    const __nv_bfloat16* __restrict__ A, int lda,
    const __nv_bfloat16* __restrict__ B, int ldb,
    const float* __restrict__ bias, const float* __restrict__ resid, int ldr,
    float* __restrict__ C, int ldc, int M, int N, int Kt,
    int rowBase, int colBase)
{
    __shared__ __nv_bfloat16 As[2][BM][BK + 8];
    __shared__ __nv_bfloat16 Bs[2][BK][BN + 8];
    __shared__ float BiasT[16][BN];

    const int tid = threadIdx.x;
    const int wid = tid >> 5;
    const int wm  = wid >> 1;
    const int wn  = wid & 1;

    wmma::fragment<wmma::accumulator, 16, 16, 16, float> acc[2][4];
#pragma unroll
    for (int mi = 0; mi < 2; mi++)
#pragma unroll
        for (int ni = 0; ni < 4; ni++) wmma::fill_fragment(acc[mi][ni], 0.f);

    for (int l = tid; l < 16 * BN; l += 256) {
        int r = l >> 7, c = l & 127;
        int gc = colBase + c;
        BiasT[r][c] = (bias != nullptr && gc < N) ? bias[gc] : 0.f;
    }

    const int aCh0 = tid * 2, bCh0 = tid * 2;
    const int nK = Kt / BK;

    {   // prologue: stage 0
#pragma unroll
        for (int u = 0; u < 2; u++) {
            int ch = aCh0 + u;
            int r = ch >> 2, c8 = (ch & 3) * 8;
            int gr = rowBase + r;
            cp_async16(&As[0][r][c8], A + (size_t)gr * lda + c8, gr < M);
        }
#pragma unroll
        for (int u = 0; u < 2; u++) {
            int ch = bCh0 + u;
            int r = ch >> 4, c8 = (ch & 15) * 8;
            cp_async16(&Bs[0][r][c8], B + (size_t)r * ldb + colBase + c8, true);
        }
        cp_commit();
    }

    for (int kt = 0; kt < nK; kt++) {
        int cur = kt & 1;
        if (kt + 1 < nK) {
            int nxt = cur ^ 1, k0 = (kt + 1) * BK;
#pragma unroll
            for (int u = 0; u < 2; u++) {
                int ch = aCh0 + u;
                int r = ch >> 2, c8 = (ch & 3) * 8;
                int gr = rowBase + r;
                cp_async16(&As[nxt][r][c8], A + (size_t)gr * lda + k0 + c8, gr < M);
            }
#pragma unroll
            for (int u = 0; u < 2; u++) {
                int ch = bCh0 + u;
                int r = ch >> 4, c8 = (ch & 15) * 8;
                cp_async16(&Bs[nxt][r][c8], B + (size_t)(k0 + r) * ldb + colBase + c8, true);
            }
            cp_commit();
            cp_wait<1>();
        } else {
            cp_wait<0>();
        }
        __syncthreads();

#pragma unroll
        for (int ks = 0; ks < BK; ks += 16) {
            wmma::fragment<wmma::matrix_a, 16, 16, 16, __nv_bfloat16, wmma::row_major> af[2];
            wmma::fragment<wmma::matrix_b, 16, 16, 16, __nv_bfloat16, wmma::row_major> bf[4];
#pragma unroll
            for (int mi = 0; mi < 2; mi++)
                wmma::load_matrix_sync(af[mi], &As[cur][wm * 32 + mi * 16][ks], BK + 8);
#pragma unroll
            for (int ni = 0; ni < 4; ni++)
                wmma::load_matrix_sync(bf[ni], &Bs[cur][ks][wn * 64 + ni * 16], BN + 8);
#pragma unroll
            for (int mi = 0; mi < 2; mi++)
#pragma unroll
                for (int ni = 0; ni < 4; ni++)
                    wmma::mma_sync(acc[mi][ni], af[mi], bf[ni], acc[mi][ni]);
        }
        __syncthreads();
    }

#pragma unroll
    for (int mi = 0; mi < 2; mi++) {
        int grow = rowBase + wm * 32 + mi * 16;
        if (grow >= M) continue;
#pragma unroll
        for (int ni = 0; ni < 4; ni++) {
            int gcol = colBase + wn * 64 + ni * 16;
            wmma::fragment<wmma::accumulator, 16, 16, 16, float> bfr;
            wmma::load_matrix_sync(bfr, &BiasT[0][wn * 64 + ni * 16], BN, wmma::mem_row_major);
            if (resid != nullptr) {
                wmma::fragment<wmma::accumulator, 16, 16, 16, float> rfr;
                wmma::load_matrix_sync(rfr, resid + (size_t)grow * ldr + gcol, ldr,
                                       wmma::mem_row_major);
#pragma unroll
                for (int i = 0; i < acc[mi][ni].num_elements; i++)
                    acc[mi][ni].x[i] += rfr.x[i];
            }
#pragma unroll
            for (int i = 0; i < acc[mi][ni].num_elements; i++) {
                float v = acc[mi][ni].x[i] + bfr.x[i];
                if (ACT == 1) v = fmaxf(v, 0.f);
                if (ACT == 2) v = (v > 0.f) ? v : 0.01f * v;
                acc[mi][ni].x[i] = v;
            }
            wmma::store_matrix_sync(C + (size_t)grow * ldc + gcol, acc[mi][ni], ldc,
                                    wmma::mem_row_major);
        }
    }
}

template <int ACT>
__global__ __launch_bounds__(256) void bgemm_kernel(
    const __nv_bfloat16* __restrict__ A, int lda,
    const __nv_bfloat16* __restrict__ B, int ldb,
    const float* bias, const float* resid, int ldr,
    float* C, int ldc, int M, int N, int Kt)
{
    bgemm_body<ACT>(A, lda, B, ldb, bias, resid, ldr, C, ldc, M, N, Kt,
                    blockIdx.x * BM, blockIdx.y * BN);
}

struct X6Args {
    const __nv_bfloat16* B[6];
    const float* bias[6];
    float*       C[6];
};
// grid (6, rowTiles): the 6 projections of one A row-tile are launch-adjacent
// -> A row-tile read from DRAM once, L2-hit by the other 5 CTAs.
__global__ __launch_bounds__(256) void bgemm_x6_kernel(
    const __nv_bfloat16* __restrict__ A, X6Args p, int M)
{
    int z = blockIdx.x;
    bgemm_body<0>(A, K3_IN, p.B[z], D_H, p.bias[z], nullptr, 0,
                  p.C[z], D_H, M, D_H, K3_IN, blockIdx.y * BM, 0);
}

// ---------------- LayerNorm over 128, warp per row -------------------------
__global__ __launch_bounds__(256) void ln128_kernel(
    const float* __restrict__ in, const float* __restrict__ gamma,
    const float* __restrict__ beta, float* __restrict__ out, int M)
{
    int row = blockIdx.x * 8 + (threadIdx.x >> 5);
    if (row >= M) return;
    int lane = threadIdx.x & 31;
    const float* p = in + (size_t)row * D_H;
    float v0 = p[lane], v1 = p[lane + 32], v2 = p[lane + 64], v3 = p[lane + 96];
    float s = v0 + v1 + v2 + v3;
#pragma unroll
    for (int o = 16; o > 0; o >>= 1) s += __shfl_xor_sync(0xFFFFFFFFu, s, o);
    float mean = s * (1.f / 128.f);
    float d0 = v0 - mean, d1 = v1 - mean, d2 = v2 - mean, d3 = v3 - mean;
    float ss = d0 * d0 + d1 * d1 + d2 * d2 + d3 * d3;
#pragma unroll
    for (int o = 16; o > 0; o >>= 1) ss += __shfl_xor_sync(0xFFFFFFFFu, ss, o);
    float inv = rsqrtf(ss * (1.f / 128.f) + 1e-5f);
    float* q = out + (size_t)row * D_H;
    q[lane]      = d0 * inv * gamma[lane]      + beta[lane];
    q[lane + 32] = d1 * inv * gamma[lane + 32] + beta[lane + 32];
    q[lane + 64] = d2 * inv * gamma[lane + 64] + beta[lane + 64];
    q[lane + 96] = d3 * inv * gamma[lane + 96] + beta[lane + 96];
}

// ---------------- edge kernels (warp per edge; edge_index is int32) --------
__global__ __launch_bounds__(256) void att_dot_kernel(
    const int* __restrict__ ei, const float* __restrict__ q,
    const float* __restrict__ k, float* __restrict__ att, int E)
{
    int e = (blockIdx.x * blockDim.x + threadIdx.x) >> 5;
    if (e >= E) return;
    int lane = threadIdx.x & 31;
    size_t s = (size_t)ei[e];
    size_t d = (size_t)ei[E + e];
    const float* qp = q + d * D_H;
    const float* kp = k + s * D_H;
    float sum = qp[lane] * kp[lane] + qp[lane + 32] * kp[lane + 32] +
                qp[lane + 64] * kp[lane + 64] + qp[lane + 96] * kp[lane + 96];
#pragma unroll
    for (int o = 16; o > 0; o >>= 1) sum += __shfl_xor_sync(0xFFFFFFFFu, sum, o);
    if (lane == 0) att[e] = sum;
}

__global__ __launch_bounds__(256) void reduce_max_p1(
    const float* __restrict__ att, int E, float* __restrict__ part)
{
    __shared__ float sm[256];
    float m = -INFINITY;
    for (int i = blockIdx.x * 256 + threadIdx.x; i < E; i += gridDim.x * 256)
        m = fmaxf(m, att[i]);
    sm[threadIdx.x] = m;
    __syncthreads();
    for (int o = 128; o > 0; o >>= 1) {
        if (threadIdx.x < o) sm[threadIdx.x] = fmaxf(sm[threadIdx.x], sm[threadIdx.x + o]);
        __syncthreads();
    }
    if (threadIdx.x == 0) part[blockIdx.x] = sm[0];
}

__global__ __launch_bounds__(512) void reduce_max_p2(
    const float* __restrict__ part, float* __restrict__ out)
{
    __shared__ float sm[512];
    sm[threadIdx.x] = part[threadIdx.x];
    __syncthreads();
    for (int o = 256; o > 0; o >>= 1) {
        if (threadIdx.x < o) sm[threadIdx.x] = fmaxf(sm[threadIdx.x], sm[threadIdx.x + o]);
        __syncthreads();
    }
    if (threadIdx.x == 0) out[0] = sm[0];
}

__global__ __launch_bounds__(256) void reduce_sum_p1(
    const float* __restrict__ att, const float* __restrict__ maxp,
    int E, float* __restrict__ part)
{
    __shared__ float sm[256];
    float mx = maxp[0];
    float s = 0.f;
    for (int i = blockIdx.x * 256 + threadIdx.x; i < E; i += gridDim.x * 256)
        s += __expf(att[i] - mx);
    sm[threadIdx.x] = s;
    __syncthreads();
    for (int o = 128; o > 0; o >>= 1) {
        if (threadIdx.x < o) sm[threadIdx.x] += sm[threadIdx.x + o];
        __syncthreads();
    }
    if (threadIdx.x == 0) part[blockIdx.x] = sm[0];
}

__global__ __launch_bounds__(512) void reduce_sum_p2(
    const float* __restrict__ part, float* __restrict__ out)
{
    __shared__ float sm[512];
    sm[threadIdx.x] = part[threadIdx.x];
    __syncthreads();
    for (int o = 256; o > 0; o >>= 1) {
        if (threadIdx.x < o) sm[threadIdx.x] += sm[threadIdx.x + o];
        __syncthreads();
    }
    if (threadIdx.x == 0) out[0] = sm[0];
}

__global__ __launch_bounds__(256) void message_kernel(
    const int* __restrict__ ei, const float* __restrict__ ea,
    const float* __restrict__ v, const float* __restrict__ hi,
    const float* __restrict__ hj, const float* __restrict__ att,
    const float* __restrict__ red, float* __restrict__ h, int E)
{
    int e = (blockIdx.x * blockDim.x + threadIdx.x) >> 5;
    if (e >= E) return;
    int lane = threadIdx.x & 31;
    size_t s = (size_t)ei[e];
    size_t d = (size_t)ei[E + e];
    float attn = __expf(att[e] - red[0]) * (1.f / red[1]);
    const float* eap = ea + (size_t)e * D_H;
    const float* vp  = v  + s * D_H;
    const float* hip = hi + s * D_H;
    const float* hjp = hj + d * D_H;
    float* hp = h + d * D_H;
#pragma unroll
    for (int c = 0; c < 4; c++) {
        int dim = lane + c * 32;
        float z = eap[dim] + hip[dim] + hjp[dim];
        float gate = 1.f / (1.f + __expf(-z));
        atomicAdd(&hp[dim], attn * vp[dim] * gate);
    }
}

// ---------------- launch ----------------------------------------------------
static inline int cdiv(int a, int b) { return (a + b - 1) / b; }

extern "C" void kernel_launch(void* const* d_in, const int* in_sizes, int n_in,
                              void* d_out, int out_size)
{
    const float* x    = (const float*)d_in[0];
    const int*   ei   = (const int*)d_in[1];
    const float* ea   = (const float*)d_in[2];
    const float* Wq   = (const float*)d_in[3];
    const float* bq   = (const float*)d_in[4];
    const float* Wk   = (const float*)d_in[5];
    const float* bk   = (const float*)d_in[6];
    const float* Wv   = (const float*)d_in[7];
    const float* bv   = (const float*)d_in[8];
    const float* Wr   = (const float*)d_in[9];
    const float* br   = (const float*)d_in[10];
    const float* Whi  = (const float*)d_in[11];
    const float* Whj  = (const float*)d_in[12];
    const float* g1   = (const float*)d_in[13];
    const float* be1  = (const float*)d_in[14];
    const float* W1   = (const float*)d_in[15];
    const float* bl1  = (const float*)d_in[16];
    const float* W2   = (const float*)d_in[17];
    const float* bl2  = (const float*)d_in[18];
    const float* g2   = (const float*)d_in[19];
    const float* be2  = (const float*)d_in[20];
    const float* Wlin = (const float*)d_in[21];
    const float* blin = (const float*)d_in[22];
    const float* Wlin2= (const float*)d_in[23];
    const float* blin2= (const float*)d_in[24];
    float* out = (float*)d_out;

    float *X, *q, *k, *v, *h, *hi, *hj, *ln, *h2, *ff, *att, *part, *red;
    __nv_bfloat16 *Xs, *lns, *ffs, *W6s, *W1s, *W2s, *Wlins, *Wl2s;
    cudaGetSymbolAddress((void**)&X,   g_X);
    cudaGetSymbolAddress((void**)&q,   g_q);
    cudaGetSymbolAddress((void**)&k,   g_k);
    cudaGetSymbolAddress((void**)&v,   g_v);
    cudaGetSymbolAddress((void**)&h,   g_h);
    cudaGetSymbolAddress((void**)&hi,  g_hi);
    cudaGetSymbolAddress((void**)&hj,  g_hj);
    cudaGetSymbolAddress((void**)&ln,  g_ln);
    cudaGetSymbolAddress((void**)&h2,  g_h2);
    cudaGetSymbolAddress((void**)&ff,  g_ff);
    cudaGetSymbolAddress((void**)&att, g_att);
    cudaGetSymbolAddress((void**)&part,g_part);
    cudaGetSymbolAddress((void**)&red, g_red);
    cudaGetSymbolAddress((void**)&Xs,  g_Xs);
    cudaGetSymbolAddress((void**)&lns, g_lns);
    cudaGetSymbolAddress((void**)&ffs, g_ffs);
    cudaGetSymbolAddress((void**)&W6s, g_W6s);
    cudaGetSymbolAddress((void**)&W1s, g_W1s);
    cudaGetSymbolAddress((void**)&W2s, g_W2s);
    cudaGetSymbolAddress((void**)&Wlins, g_Wlins);
    cudaGetSymbolAddress((void**)&Wl2s,  g_Wl2s);

    const int M = NNODE, E = NEDGE;
    const int rowTiles = cdiv(M, BM);
    const int edgeBlocks = (E * 32 + 255) / 256;
    const int lnBlocks = (M + 7) / 8;

    // shared weights: split once
    splitB_kernel<<<cdiv(D_H * NP_LIN, 256), 256>>>(Wlin,  D_H,  D_IN, D_H,  NP_LIN, Wlins);
    splitB_kernel<<<cdiv(KP_IN * D_H, 256), 256>>>(Wlin2, D_IN, D_H,  KP_IN, D_H,   Wl2s);

    const float* xin = x;
    int lda = D_IN;
    for (int i = 0; i < 2; i++) {
        splitA_kernel<<<cdiv(M * KP_IN, 256), 256>>>(xin, lda, M, D_IN, KP_IN, Xs);
        const float* Wp[6] = { Wq + (size_t)i * D_IN * D_H, Wk + (size_t)i * D_IN * D_H,
                               Wv + (size_t)i * D_IN * D_H, Wr + (size_t)i * D_IN * D_H,
                               Whi + (size_t)i * D_IN * D_H, Whj + (size_t)i * D_IN * D_H };
        for (int z = 0; z < 6; z++)
            splitB_kernel<<<cdiv(KP_IN * D_H, 256), 256>>>(
                Wp[z], D_IN, D_H, KP_IN, D_H, W6s + (size_t)z * K3_IN * D_H);

        // 1) fused 6-way projection (grid: 6 x rowTiles for L2 A reuse)
        X6Args a;
        for (int z = 0; z < 6; z++) a.B[z] = W6s + (size_t)z * K3_IN * D_H;
        a.bias[0] = bq + (size_t)i * D_H;  a.C[0] = q;
        a.bias[1] = bk + (size_t)i * D_H;  a.C[1] = k;
        a.bias[2] = bv + (size_t)i * D_H;  a.C[2] = v;
        a.bias[3] = br + (size_t)i * D_H;  a.C[3] = h;
        a.bias[4] = nullptr;               a.C[4] = hi;
        a.bias[5] = nullptr;               a.C[5] = hj;
        bgemm_x6_kernel<<<dim3(6, rowTiles), 256>>>(Xs, a, M);

        // 2) attention + global softmax stats
        att_dot_kernel<<<edgeBlocks, 256>>>(ei, q, k, att, E);
        reduce_max_p1<<<512, 256>>>(att, E, part);
        reduce_max_p2<<<1, 512>>>(part, red);
        reduce_sum_p1<<<512, 256>>>(att, red, E, part);
        reduce_sum_p2<<<1, 512>>>(part, red + 1);

        // 3) gated messages scatter-added onto h
        message_kernel<<<edgeBlocks, 256>>>(ei, ea, v, hi, hj, att, red, h, E);

        // 4) FF MLP with pre-norm residual
        ln128_kernel<<<lnBlocks, 256>>>(h, g1 + (size_t)i * D_H, be1 + (size_t)i * D_H, ln, M);
        splitA_kernel<<<cdiv(M * D_H, 256), 256>>>(ln, D_H, M, D_H, D_H, lns);
        splitB_kernel<<<cdiv(D_H * D_FF, 256), 256>>>(
            W1 + (size_t)i * D_H * D_FF, D_H, D_FF, D_H, D_FF, W1s);
        bgemm_kernel<1><<<dim3(rowTiles, D_FF / BN), 256>>>(
            lns, K3_H, W1s, D_FF, bl1 + (size_t)i * D_FF, nullptr, 0,
            ff, D_FF, M, D_FF, K3_H);
        splitA_kernel<<<cdiv(M * D_FF, 256), 256>>>(ff, D_FF, M, D_FF, D_FF, ffs);
        splitB_kernel<<<cdiv(D_FF * D_H, 256), 256>>>(
            W2 + (size_t)i * D_FF * D_H, D_FF, D_H, D_FF, D_H, W2s);
        bgemm_kernel<0><<<dim3(rowTiles, 1), 256>>>(
            ffs, K3_FF, W2s, D_H, bl2 + (size_t)i * D_H, h, D_H,
            h2, D_H, M, D_H, K3_FF);
        ln128_kernel<<<lnBlocks, 256>>>(h2, g2 + (size_t)i * D_H, be2 + (size_t)i * D_H, ln, M);

        // 5) expand back to 1546 (into padded-stride fp32 X)
        splitA_kernel<<<cdiv(M * D_H, 256), 256>>>(ln, D_H, M, D_H, D_H, lns);
        bgemm_kernel<0><<<dim3(rowTiles, NP_LIN / BN), 256>>>(
            lns, K3_H, Wlins, NP_LIN, blin, nullptr, 0,
            X, XSTRIDE, M, D_IN, K3_H);
        xin = X;
        lda = XSTRIDE;
    }

    // final: leaky_relu(X @ Wlin2 + blin2)
    splitA_kernel<<<cdiv(M * KP_IN, 256), 256>>>(X, XSTRIDE, M, D_IN, KP_IN, Xs);
    bgemm_kernel<2><<<dim3(rowTiles, 1), 256>>>(
        Xs, K3_IN, Wl2s, D_H, blin2, nullptr, 0,
        out, D_H, M, D_H, K3_IN);
}

// round 15
// speedup vs baseline: 1.4275x; 1.0142x over previous
#include <cuda_runtime.h>
#include <cuda_bf16.h>
#include <mma.h>
#include <math.h>
#include <cstdint>

using namespace nvcuda;

#define NNODE 20000
#define NEDGE 400000
#define D_IN  1546
#define D_H   128
#define D_FF  512
#define XSTRIDE 1664   // fp32 X buffer stride

#define KP_IN 1568     // D_IN padded to mult of 32
#define K3_IN (3 * KP_IN)    // 4704
#define K3_H  (3 * D_H)      // 384
#define K3_FF (3 * D_FF)     // 1536
#define NP_LIN 1664    // Wlin'' col stride

#define BM 128
#define BN 128
#define BK 32
#define APAD 40
#define BPAD 136
#define NSTAGE 3

// dynamic smem layout (bytes)
#define SM_B_OFF    (NSTAGE * BM * APAD * 2)             // 30720
#define SM_BIAS_OFF (SM_B_OFF + NSTAGE * BK * BPAD * 2)  // 56832
#define SM_TOTAL    (SM_BIAS_OFF + 16 * BN * 4)          // 65024

// ---------------- scratch (device globals; no allocations) ----------------
__device__ float g_X [NNODE * XSTRIDE];
__device__ float g_q [NNODE * D_H];
__device__ float g_k [NNODE * D_H];
__device__ float g_v [NNODE * D_H];
__device__ float g_h [NNODE * D_H];
__device__ float g_hi[NNODE * D_H];
__device__ float g_hj[NNODE * D_H];
__device__ float g_ln[NNODE * D_H];
__device__ float g_h2[NNODE * D_H];
__device__ float g_ff[NNODE * D_FF];
__device__ float g_att[NEDGE];
__device__ float g_part[512];
__device__ float g_red[2];

// bf16 split operands (A'' blocks hi,hi,lo ; B'' blocks hi,lo,hi)
__device__ __nv_bfloat16 g_Xs   [(size_t)NNODE * K3_IN];
__device__ __nv_bfloat16 g_lns  [(size_t)NNODE * K3_H];
__device__ __nv_bfloat16 g_ffs  [(size_t)NNODE * K3_FF];
__device__ __nv_bfloat16 g_W6s  [(size_t)12 * K3_IN * D_H];   // both layers
__device__ __nv_bfloat16 g_W1s  [(size_t)2 * K3_H * D_FF];
__device__ __nv_bfloat16 g_W2s  [(size_t)2 * K3_FF * D_H];
__device__ __nv_bfloat16 g_Wlins[(size_t)K3_H * NP_LIN];
__device__ __nv_bfloat16 g_Wl2s [(size_t)K3_IN * D_H];

// ---------------- cp.async helpers -----------------------------------------
__device__ __forceinline__ void cp_async16(void* smem_dst, const void* gsrc, bool pred) {
    uint32_t saddr = (uint32_t)__cvta_generic_to_shared(smem_dst);
    int sz = pred ? 16 : 0;
    asm volatile("cp.async.cg.shared.global [%0], [%1], 16, %2;\n"
                 :: "r"(saddr), "l"(gsrc), "r"(sz));
}
__device__ __forceinline__ void cp_commit() { asm volatile("cp.async.commit_group;\n"); }
template <int NREM>
__device__ __forceinline__ void cp_wait() { asm volatile("cp.async.wait_group %0;\n" :: "n"(NREM)); }

// ---------------- split kernels ---------------------------------------------
// A'' (M x 3Kp): stacked hi@0, hi@Kp, lo@2Kp
__global__ __launch_bounds__(256) void splitA_kernel(
    const float* __restrict__ in, int lda, int M, int K, int Kp,
    __nv_bfloat16* __restrict__ out)
{
    int idx = blockIdx.x * 256 + threadIdx.x;
    int total = M * Kp;
    if (idx >= total) return;
    int r = idx / Kp, c = idx - r * Kp;
    float v = (c < K) ? in[(size_t)r * lda + c] : 0.f;
    __nv_bfloat16 hi = __float2bfloat16(v);
    __nv_bfloat16 lo = __float2bfloat16(v - __bfloat162float(hi));
    size_t base = (size_t)r * (3 * Kp);
    out[base + c]          = hi;
    out[base + Kp + c]     = hi;
    out[base + 2 * Kp + c] = lo;
}

// batched B'' split over grid.z layers: rows [hi; lo; hi]
__global__ __launch_bounds__(256) void splitBb_kernel(
    const float* __restrict__ in, int K, int N, int Kp, int NP,
    size_t inLayerStride, size_t outLayerStride, __nv_bfloat16* __restrict__ out)
{
    int z = blockIdx.z;
    int idx = blockIdx.x * 256 + threadIdx.x;
    if (idx >= Kp * NP) return;
    int r = idx / NP, c = idx - r * NP;
    const float* ip = in + (size_t)z * inLayerStride;
    __nv_bfloat16* op = out + (size_t)z * outLayerStride;
    float v = (r < K && c < N) ? ip[(size_t)r * N + c] : 0.f;
    __nv_bfloat16 hi = __float2bfloat16(v);
    __nv_bfloat16 lo = __float2bfloat16(v - __bfloat162float(hi));
    op[(size_t)r * NP + c]            = hi;
    op[(size_t)(Kp + r) * NP + c]     = lo;
    op[(size_t)(2 * Kp + r) * NP + c] = hi;
}

// all 12 projection weights (2 layers x 6 types) in one launch (grid.z = 12)
struct W6Ptrs { const float* p[6]; };
__global__ __launch_bounds__(256) void splitW6_kernel(
    W6Ptrs w, __nv_bfloat16* __restrict__ out)
{
    int z = blockIdx.z;             // l*6 + t
    int l = z / 6, t = z - l * 6;
    int idx = blockIdx.x * 256 + threadIdx.x;
    if (idx >= KP_IN * D_H) return;
    int r = idx / D_H, c = idx - r * D_H;
    float v = (r < D_IN) ? w.p[t][(size_t)l * D_IN * D_H + (size_t)r * D_H + c] : 0.f;
    __nv_bfloat16 hi = __float2bfloat16(v);
    __nv_bfloat16 lo = __float2bfloat16(v - __bfloat162float(hi));
    __nv_bfloat16* o = out + (size_t)z * K3_IN * D_H;
    o[(size_t)r * D_H + c]                = hi;
    o[(size_t)(KP_IN + r) * D_H + c]      = lo;
    o[(size_t)(2 * KP_IN + r) * D_H + c]  = hi;
}

// ---------------- bf16 tensor-core GEMM (BK=32, 3-stage, 1 bar/iter) -------
template <int ACT>  // 0=none, 1=relu, 2=leaky(0.01)
__device__ __forceinline__ void bgemm_body(
    const __nv_bfloat16* __restrict__ A, int lda,
    const __nv_bfloat16* __restrict__ B, int ldb,
    const float* __restrict__ bias, const float* __restrict__ resid, int ldr,
    float* __restrict__ C, int ldc, int M, int N, int Kt,
    int rowBase, int colBase)
{
    extern __shared__ char smraw[];
    __nv_bfloat16 (*As)[BM][APAD] = reinterpret_cast<__nv_bfloat16 (*)[BM][APAD]>(smraw);
    __nv_bfloat16 (*Bs)[BK][BPAD] = reinterpret_cast<__nv_bfloat16 (*)[BK][BPAD]>(smraw + SM_B_OFF);
    float (*BiasT)[BN] = reinterpret_cast<float (*)[BN]>(smraw + SM_BIAS_OFF);

    const int tid = threadIdx.x;
    const int wid = tid >> 5;
    const int wm  = wid >> 1;
    const int wn  = wid & 1;

    wmma::fragment<wmma::accumulator, 16, 16, 16, float> acc[2][4];
#pragma unroll
    for (int mi = 0; mi < 2; mi++)
#pragma unroll
        for (int ni = 0; ni < 4; ni++) wmma::fill_fragment(acc[mi][ni], 0.f);

    for (int l = tid; l < 16 * BN; l += 256) {
        int r = l >> 7, c = l & 127;
        int gc = colBase + c;
        BiasT[r][c] = (bias != nullptr && gc < N) ? bias[gc] : 0.f;
    }

    const int nK = Kt / BK;

    // per-thread loader chunks: 2 A-chunks + 2 B-chunks of 16B
    auto loadStage = [&](int st, int k0) {
#pragma unroll
        for (int u = 0; u < 2; u++) {
            int ch = tid * 2 + u;
            int r = ch >> 2, c8 = (ch & 3) * 8;
            int gr = rowBase + r;
            cp_async16(&As[st][r][c8], A + (size_t)gr * lda + k0 + c8, gr < M);
        }
#pragma unroll
        for (int u = 0; u < 2; u++) {
            int ch = tid * 2 + u;
            int r = ch >> 4, c8 = (ch & 15) * 8;
            cp_async16(&Bs[st][r][c8], B + (size_t)(k0 + r) * ldb + colBase + c8, true);
        }
        cp_commit();
    };

    loadStage(0, 0);
    if (nK > 1) loadStage(1, BK);

    for (int kt = 0; kt < nK; kt++) {
        int cur = kt % NSTAGE;
        if (kt + 1 < nK) cp_wait<1>(); else cp_wait<0>();
        __syncthreads();   // data of stage `cur` visible; all warps done with slot (kt+2)%3
        if (kt + 2 < nK) loadStage((kt + 2) % NSTAGE, (kt + 2) * BK);

#pragma unroll
        for (int ks = 0; ks < BK; ks += 16) {
            wmma::fragment<wmma::matrix_a, 16, 16, 16, __nv_bfloat16, wmma::row_major> af[2];
            wmma::fragment<wmma::matrix_b, 16, 16, 16, __nv_bfloat16, wmma::row_major> bf[4];
#pragma unroll
            for (int mi = 0; mi < 2; mi++)
                wmma::load_matrix_sync(af[mi], &As[cur][wm * 32 + mi * 16][ks], APAD);
#pragma unroll
            for (int ni = 0; ni < 4; ni++)
                wmma::load_matrix_sync(bf[ni], &Bs[cur][ks][wn * 64 + ni * 16], BPAD);
#pragma unroll
            for (int mi = 0; mi < 2; mi++)
#pragma unroll
                for (int ni = 0; ni < 4; ni++)
                    wmma::mma_sync(acc[mi][ni], af[mi], bf[ni], acc[mi][ni]);
        }
    }
    __syncthreads();

#pragma unroll
    for (int mi = 0; mi < 2; mi++) {
        int grow = rowBase + wm * 32 + mi * 16;
        if (grow >= M) continue;
#pragma unroll
        for (int ni = 0; ni < 4; ni++) {
            int gcol = colBase + wn * 64 + ni * 16;
            wmma::fragment<wmma::accumulator, 16, 16, 16, float> bfr;
            wmma::load_matrix_sync(bfr, &BiasT[0][wn * 64 + ni * 16], BN, wmma::mem_row_major);
            if (resid != nullptr) {
                wmma::fragment<wmma::accumulator, 16, 16, 16, float> rfr;
                wmma::load_matrix_sync(rfr, resid + (size_t)grow * ldr + gcol, ldr,
                                       wmma::mem_row_major);
#pragma unroll
                for (int i = 0; i < acc[mi][ni].num_elements; i++)
                    acc[mi][ni].x[i] += rfr.x[i];
            }
#pragma unroll
            for (int i = 0; i < acc[mi][ni].num_elements; i++) {
                float v = acc[mi][ni].x[i] + bfr.x[i];
                if (ACT == 1) v = fmaxf(v, 0.f);
                if (ACT == 2) v = (v > 0.f) ? v : 0.01f * v;
                acc[mi][ni].x[i] = v;
            }
            wmma::store_matrix_sync(C + (size_t)grow * ldc + gcol, acc[mi][ni], ldc,
                                    wmma::mem_row_major);
        }
    }
}

template <int ACT>
__global__ __launch_bounds__(256, 2) void bgemm_kernel(
    const __nv_bfloat16* __restrict__ A, int lda,
    const __nv_bfloat16* __restrict__ B, int ldb,
    const float* bias, const float* resid, int ldr,
    float* C, int ldc, int M, int N, int Kt)
{
    bgemm_body<ACT>(A, lda, B, ldb, bias, resid, ldr, C, ldc, M, N, Kt,
                    blockIdx.x * BM, blockIdx.y * BN);
}

struct X6Args {
    const __nv_bfloat16* B[6];
    const float* bias[6];
    float*       C[6];
};
__global__ __launch_bounds__(256, 2) void bgemm_x6_kernel(
    const __nv_bfloat16* __restrict__ A, X6Args p, int M)
{
    int z = blockIdx.x;
    bgemm_body<0>(A, K3_IN, p.B[z], D_H, p.bias[z], nullptr, 0,
                  p.C[z], D_H, M, D_H, K3_IN, blockIdx.y * BM, 0);
}

// ---------------- LayerNorm over 128, warp per row -------------------------
__global__ __launch_bounds__(256) void ln128_kernel(
    const float* __restrict__ in, const float* __restrict__ gamma,
    const float* __restrict__ beta, float* __restrict__ out, int M)
{
    int row = blockIdx.x * 8 + (threadIdx.x >> 5);
    if (row >= M) return;
    int lane = threadIdx.x & 31;
    const float* p = in + (size_t)row * D_H;
    float v0 = p[lane], v1 = p[lane + 32], v2 = p[lane + 64], v3 = p[lane + 96];
    float s = v0 + v1 + v2 + v3;
#pragma unroll
    for (int o = 16; o > 0; o >>= 1) s += __shfl_xor_sync(0xFFFFFFFFu, s, o);
    float mean = s * (1.f / 128.f);
    float d0 = v0 - mean, d1 = v1 - mean, d2 = v2 - mean, d3 = v3 - mean;
    float ss = d0 * d0 + d1 * d1 + d2 * d2 + d3 * d3;
#pragma unroll
    for (int o = 16; o > 0; o >>= 1) ss += __shfl_xor_sync(0xFFFFFFFFu, ss, o);
    float inv = rsqrtf(ss * (1.f / 128.f) + 1e-5f);
    float* q = out + (size_t)row * D_H;
    q[lane]      = d0 * inv * gamma[lane]      + beta[lane];
    q[lane + 32] = d1 * inv * gamma[lane + 32] + beta[lane + 32];
    q[lane + 64] = d2 * inv * gamma[lane + 64] + beta[lane + 64];
    q[lane + 96] = d3 * inv * gamma[lane + 96] + beta[lane + 96];
}

// ---------------- edge kernels (warp per edge; edge_index is int32) --------
__global__ __launch_bounds__(256) void att_dot_kernel(
    const int* __restrict__ ei, const float* __restrict__ q,
    const float* __restrict__ k, float* __restrict__ att, int E)
{
    int e = (blockIdx.x * blockDim.x + threadIdx.x) >> 5;
    if (e >= E) return;
    int lane = threadIdx.x & 31;
    size_t s = (size_t)ei[e];
    size_t d = (size_t)ei[E + e];
    const float* qp = q + d * D_H;
    const float* kp = k + s * D_H;
    float sum = qp[lane] * kp[lane] + qp[lane + 32] * kp[lane + 32] +
                qp[lane + 64] * kp[lane + 64] + qp[lane + 96] * kp[lane + 96];
#pragma unroll
    for (int o = 16; o > 0; o >>= 1) sum += __shfl_xor_sync(0xFFFFFFFFu, sum, o);
    if (lane == 0) att[e] = sum;
}

__global__ __launch_bounds__(256) void reduce_max_p1(
    const float* __restrict__ att, int E, float* __restrict__ part)
{
    __shared__ float sm[256];
    float m = -INFINITY;
    for (int i = blockIdx.x * 256 + threadIdx.x; i < E; i += gridDim.x * 256)
        m = fmaxf(m, att[i]);
    sm[threadIdx.x] = m;
    __syncthreads();
    for (int o = 128; o > 0; o >>= 1) {
        if (threadIdx.x < o) sm[threadIdx.x] = fmaxf(sm[threadIdx.x], sm[threadIdx.x + o]);
        __syncthreads();
    }
    if (threadIdx.x == 0) part[blockIdx.x] = sm[0];
}

__global__ __launch_bounds__(512) void reduce_max_p2(
    const float* __restrict__ part, float* __restrict__ out)
{
    __shared__ float sm[512];
    sm[threadIdx.x] = part[threadIdx.x];
    __syncthreads();
    for (int o = 256; o > 0; o >>= 1) {
        if (threadIdx.x < o) sm[threadIdx.x] = fmaxf(sm[threadIdx.x], sm[threadIdx.x + o]);
        __syncthreads();
    }
    if (threadIdx.x == 0) out[0] = sm[0];
}

__global__ __launch_bounds__(256) void reduce_sum_p1(
    const float* __restrict__ att, const float* __restrict__ maxp,
    int E, float* __restrict__ part)
{
    __shared__ float sm[256];
    float mx = maxp[0];
    float s = 0.f;
    for (int i = blockIdx.x * 256 + threadIdx.x; i < E; i += gridDim.x * 256)
        s += __expf(att[i] - mx);
    sm[threadIdx.x] = s;
    __syncthreads();
    for (int o = 128; o > 0; o >>= 1) {
        if (threadIdx.x < o) sm[threadIdx.x] += sm[threadIdx.x + o];
        __syncthreads();
    }
    if (threadIdx.x == 0) part[blockIdx.x] = sm[0];
}

__global__ __launch_bounds__(512) void reduce_sum_p2(
    const float* __restrict__ part, float* __restrict__ out)
{
    __shared__ float sm[512];
    sm[threadIdx.x] = part[threadIdx.x];
    __syncthreads();
    for (int o = 256; o > 0; o >>= 1) {
        if (threadIdx.x < o) sm[threadIdx.x] += sm[threadIdx.x + o];
        __syncthreads();
    }
    if (threadIdx.x == 0) out[0] = sm[0];
}

__global__ __launch_bounds__(256) void message_kernel(
    const int* __restrict__ ei, const float* __restrict__ ea,
    const float* __restrict__ v, const float* __restrict__ hi,
    const float* __restrict__ hj, const float* __restrict__ att,
    const float* __restrict__ red, float* __restrict__ h, int E)
{
    int e = (blockIdx.x * blockDim.x + threadIdx.x) >> 5;
    if (e >= E) return;
    int lane = threadIdx.x & 31;
    size_t s = (size_t)ei[e];
    size_t d = (size_t)ei[E + e];
    float attn = __expf(att[e] - red[0]) * (1.f / red[1]);
    const float* eap = ea + (size_t)e * D_H;
    const float* vp  = v  + s * D_H;
    const float* hip = hi + s * D_H;
    const float* hjp = hj + d * D_H;
    float* hp = h + d * D_H;
#pragma unroll
    for (int c = 0; c < 4; c++) {
        int dim = lane + c * 32;
        float z = eap[dim] + hip[dim] + hjp[dim];
        float gate = 1.f / (1.f + __expf(-z));
        atomicAdd(&hp[dim], attn * vp[dim] * gate);
    }
}

// ---------------- launch ----------------------------------------------------
static inline int cdiv(int a, int b) { return (a + b - 1) / b; }

extern "C" void kernel_launch(void* const* d_in, const int* in_sizes, int n_in,
                              void* d_out, int out_size)
{
    const float* x    = (const float*)d_in[0];
    const int*   ei   = (const int*)d_in[1];
    const float* ea   = (const float*)d_in[2];
    const float* Wq   = (const float*)d_in[3];
    const float* bq   = (const float*)d_in[4];
    const float* Wk   = (const float*)d_in[5];
    const float* bk   = (const float*)d_in[6];
    const float* Wv   = (const float*)d_in[7];
    const float* bv   = (const float*)d_in[8];
    const float* Wr   = (const float*)d_in[9];
    const float* br   = (const float*)d_in[10];
    const float* Whi  = (const float*)d_in[11];
    const float* Whj  = (const float*)d_in[12];
    const float* g1   = (const float*)d_in[13];
    const float* be1  = (const float*)d_in[14];
    const float* W1   = (const float*)d_in[15];
    const float* bl1  = (const float*)d_in[16];
    const float* W2   = (const float*)d_in[17];
    const float* bl2  = (const float*)d_in[18];
    const float* g2   = (const float*)d_in[19];
    const float* be2  = (const float*)d_in[20];
    const float* Wlin = (const float*)d_in[21];
    const float* blin = (const float*)d_in[22];
    const float* Wlin2= (const float*)d_in[23];
    const float* blin2= (const float*)d_in[24];
    float* out = (float*)d_out;

    float *X, *q, *k, *v, *h, *hi, *hj, *ln, *h2, *ff, *att, *part, *red;
    __nv_bfloat16 *Xs, *lns, *ffs, *W6s, *W1s, *W2s, *Wlins, *Wl2s;
    cudaGetSymbolAddress((void**)&X,   g_X);
    cudaGetSymbolAddress((void**)&q,   g_q);
    cudaGetSymbolAddress((void**)&k,   g_k);
    cudaGetSymbolAddress((void**)&v,   g_v);
    cudaGetSymbolAddress((void**)&h,   g_h);
    cudaGetSymbolAddress((void**)&hi,  g_hi);
    cudaGetSymbolAddress((void**)&hj,  g_hj);
    cudaGetSymbolAddress((void**)&ln,  g_ln);
    cudaGetSymbolAddress((void**)&h2,  g_h2);
    cudaGetSymbolAddress((void**)&ff,  g_ff);
    cudaGetSymbolAddress((void**)&att, g_att);
    cudaGetSymbolAddress((void**)&part,g_part);
    cudaGetSymbolAddress((void**)&red, g_red);
    cudaGetSymbolAddress((void**)&Xs,  g_Xs);
    cudaGetSymbolAddress((void**)&lns, g_lns);
    cudaGetSymbolAddress((void**)&ffs, g_ffs);
    cudaGetSymbolAddress((void**)&W6s, g_W6s);
    cudaGetSymbolAddress((void**)&W1s, g_W1s);
    cudaGetSymbolAddress((void**)&W2s, g_W2s);
    cudaGetSymbolAddress((void**)&Wlins, g_Wlins);
    cudaGetSymbolAddress((void**)&Wl2s,  g_Wl2s);

    cudaFuncSetAttribute(bgemm_kernel<0>, cudaFuncAttributeMaxDynamicSharedMemorySize, SM_TOTAL);
    cudaFuncSetAttribute(bgemm_kernel<1>, cudaFuncAttributeMaxDynamicSharedMemorySize, SM_TOTAL);
    cudaFuncSetAttribute(bgemm_kernel<2>, cudaFuncAttributeMaxDynamicSharedMemorySize, SM_TOTAL);
    cudaFuncSetAttribute(bgemm_x6_kernel, cudaFuncAttributeMaxDynamicSharedMemorySize, SM_TOTAL);

    const int M = NNODE, E = NEDGE;
    const int rowTiles = cdiv(M, BM);
    const int edgeBlocks = (E * 32 + 255) / 256;
    const int lnBlocks = (M + 7) / 8;

    // launch 0: split layer-0 input
    splitA_kernel<<<cdiv(M * KP_IN, 256), 256>>>(x, D_IN, M, D_IN, KP_IN, Xs);
    // launches 1-4: all weight splits except W2 (placed so bgemm_x6 is launch 5)
    splitBb_kernel<<<dim3(cdiv(D_H * NP_LIN, 256), 1, 1), 256>>>(
        Wlin, D_H, D_IN, D_H, NP_LIN, 0, 0, Wlins);
    splitBb_kernel<<<dim3(cdiv(KP_IN * D_H, 256), 1, 1), 256>>>(
        Wlin2, D_IN, D_H, KP_IN, D_H, 0, 0, Wl2s);
    W6Ptrs wp; wp.p[0]=Wq; wp.p[1]=Wk; wp.p[2]=Wv; wp.p[3]=Wr; wp.p[4]=Whi; wp.p[5]=Whj;
    splitW6_kernel<<<dim3(cdiv(KP_IN * D_H, 256), 1, 12), 256>>>(wp, W6s);
    splitBb_kernel<<<dim3(cdiv(D_H * D_FF, 256), 1, 2), 256>>>(
        W1, D_H, D_FF, D_H, D_FF, (size_t)D_H * D_FF, (size_t)K3_H * D_FF, W1s);

    for (int i = 0; i < 2; i++) {
        // 1) fused 6-way projection (launch 5 on first iteration -> ncu window)
        X6Args a;
        for (int z = 0; z < 6; z++) a.B[z] = W6s + (size_t)(i * 6 + z) * K3_IN * D_H;
        a.bias[0] = bq + (size_t)i * D_H;  a.C[0] = q;
        a.bias[1] = bk + (size_t)i * D_H;  a.C[1] = k;
        a.bias[2] = bv + (size_t)i * D_H;  a.C[2] = v;
        a.bias[3] = br + (size_t)i * D_H;  a.C[3] = h;
        a.bias[4] = nullptr;               a.C[4] = hi;
        a.bias[5] = nullptr;               a.C[5] = hj;
        bgemm_x6_kernel<<<dim3(6, rowTiles), 256, SM_TOTAL>>>(Xs, a, M);

        if (i == 0)  // W2 split (both layers), after the profiled launch
            splitBb_kernel<<<dim3(cdiv(D_FF * D_H, 256), 1, 2), 256>>>(
                W2, D_FF, D_H, D_FF, D_H, (size_t)D_FF * D_H, (size_t)K3_FF * D_H, W2s);

        // 2) attention + global softmax stats
        att_dot_kernel<<<edgeBlocks, 256>>>(ei, q, k, att, E);
        reduce_max_p1<<<512, 256>>>(att, E, part);
        reduce_max_p2<<<1, 512>>>(part, red);
        reduce_sum_p1<<<512, 256>>>(att, red, E, part);
        reduce_sum_p2<<<1, 512>>>(part, red + 1);

        // 3) gated messages scatter-added onto h
        message_kernel<<<edgeBlocks, 256>>>(ei, ea, v, hi, hj, att, red, h, E);

        // 4) FF MLP with pre-norm residual
        ln128_kernel<<<lnBlocks, 256>>>(h, g1 + (size_t)i * D_H, be1 + (size_t)i * D_H, ln, M);
        splitA_kernel<<<cdiv(M * D_H, 256), 256>>>(ln, D_H, M, D_H, D_H, lns);
        bgemm_kernel<1><<<dim3(rowTiles, D_FF / BN), 256, SM_TOTAL>>>(
            lns, K3_H, W1s + (size_t)i * K3_H * D_FF, D_FF, bl1 + (size_t)i * D_FF, nullptr, 0,
            ff, D_FF, M, D_FF, K3_H);
        splitA_kernel<<<cdiv(M * D_FF, 256), 256>>>(ff, D_FF, M, D_FF, D_FF, ffs);
        bgemm_kernel<0><<<dim3(rowTiles, 1), 256, SM_TOTAL>>>(
            ffs, K3_FF, W2s + (size_t)i * K3_FF * D_H, D_H, bl2 + (size_t)i * D_H, h, D_H,
            h2, D_H, M, D_H, K3_FF);
        ln128_kernel<<<lnBlocks, 256>>>(h2, g2 + (size_t)i * D_H, be2 + (size_t)i * D_H, ln, M);

        // 5) expand back to 1546, then split for the next consumer
        splitA_kernel<<<cdiv(M * D_H, 256), 256>>>(ln, D_H, M, D_H, D_H, lns);
        bgemm_kernel<0><<<dim3(rowTiles, NP_LIN / BN), 256, SM_TOTAL>>>(
            lns, K3_H, Wlins, NP_LIN, blin, nullptr, 0,
            X, XSTRIDE, M, D_IN, K3_H);
        splitA_kernel<<<cdiv(M * KP_IN, 256), 256>>>(X, XSTRIDE, M, D_IN, KP_IN, Xs);
    }

    // final: leaky_relu(X @ Wlin2 + blin2)
    bgemm_kernel<2><<<dim3(rowTiles, 1), 256, SM_TOTAL>>>(
        Xs, K3_IN, Wl2s, D_H, blin2, nullptr, 0,
        out, D_H, M, D_H, K3_IN);
}

// round 16
// speedup vs baseline: 1.7084x; 1.1967x over previous
#include <cuda_runtime.h>
#include <cuda_bf16.h>
#include <mma.h>
#include <math.h>
#include <cstdint>

using namespace nvcuda;

#define NNODE 20000
#define NEDGE 400000
#define D_IN  1546
#define D_H   128
#define D_FF  512
#define XSTRIDE 1664   // fp32 X buffer stride

#define KP_IN 1568     // D_IN padded to mult of 32
#define K3_IN (3 * KP_IN)    // 4704
#define K3_H  (3 * D_H)      // 384
#define K3_FF (3 * D_FF)     // 1536
#define NP_LIN 1664    // Wlin'' col stride

#define BM 128
#define BN 128
#define BK 32
#define APAD 40
#define BPAD 136
#define NSTAGE 3
#define NTHREADS 128   // 4 warps, 2x2 grid of 64x64 warp tiles

// dynamic smem layout (bytes)
#define SM_B_OFF    (NSTAGE * BM * APAD * 2)             // 30720
#define SM_BIAS_OFF (SM_B_OFF + NSTAGE * BK * BPAD * 2)  // 56832
#define SM_TOTAL    (SM_BIAS_OFF + 16 * BN * 4)          // 65024

// ---------------- scratch (device globals; no allocations) ----------------
__device__ float g_X [NNODE * XSTRIDE];
__device__ float g_q [NNODE * D_H];
__device__ float g_k [NNODE * D_H];
__device__ float g_v [NNODE * D_H];
__device__ float g_h [NNODE * D_H];
__device__ float g_hi[NNODE * D_H];
__device__ float g_hj[NNODE * D_H];
__device__ float g_ln[NNODE * D_H];
__device__ float g_h2[NNODE * D_H];
__device__ float g_ff[NNODE * D_FF];
__device__ float g_att[NEDGE];
__device__ float g_part[512];
__device__ float g_red[2];

// bf16 split operands (A'' blocks hi,hi,lo ; B'' blocks hi,lo,hi)
__device__ __nv_bfloat16 g_Xs   [(size_t)NNODE * K3_IN];
__device__ __nv_bfloat16 g_lns  [(size_t)NNODE * K3_H];
__device__ __nv_bfloat16 g_ffs  [(size_t)NNODE * K3_FF];
__device__ __nv_bfloat16 g_W6s  [(size_t)12 * K3_IN * D_H];
__device__ __nv_bfloat16 g_W1s  [(size_t)2 * K3_H * D_FF];
__device__ __nv_bfloat16 g_W2s  [(size_t)2 * K3_FF * D_H];
__device__ __nv_bfloat16 g_Wlins[(size_t)K3_H * NP_LIN];
__device__ __nv_bfloat16 g_Wl2s [(size_t)K3_IN * D_H];

// ---------------- cp.async helpers -----------------------------------------
__device__ __forceinline__ void cp_async16(void* smem_dst, const void* gsrc, bool pred) {
    uint32_t saddr = (uint32_t)__cvta_generic_to_shared(smem_dst);
    int sz = pred ? 16 : 0;
    asm volatile("cp.async.cg.shared.global [%0], [%1], 16, %2;\n"
                 :: "r"(saddr), "l"(gsrc), "r"(sz));
}
__device__ __forceinline__ void cp_commit() { asm volatile("cp.async.commit_group;\n"); }
template <int NREM>
__device__ __forceinline__ void cp_wait() { asm volatile("cp.async.wait_group %0;\n" :: "n"(NREM)); }

// ---------------- split kernels ---------------------------------------------
__global__ __launch_bounds__(256) void splitA_kernel(
    const float* __restrict__ in, int lda, int M, int K, int Kp,
    __nv_bfloat16* __restrict__ out)
{
    int idx = blockIdx.x * 256 + threadIdx.x;
    int total = M * Kp;
    if (idx >= total) return;
    int r = idx / Kp, c = idx - r * Kp;
    float v = (c < K) ? in[(size_t)r * lda + c] : 0.f;
    __nv_bfloat16 hi = __float2bfloat16(v);
    __nv_bfloat16 lo = __float2bfloat16(v - __bfloat162float(hi));
    size_t base = (size_t)r * (3 * Kp);
    out[base + c]          = hi;
    out[base + Kp + c]     = hi;
    out[base + 2 * Kp + c] = lo;
}

__global__ __launch_bounds__(256) void splitBb_kernel(
    const float* __restrict__ in, int K, int N, int Kp, int NP,
    size_t inLayerStride, size_t outLayerStride, __nv_bfloat16* __restrict__ out)
{
    int z = blockIdx.z;
    int idx = blockIdx.x * 256 + threadIdx.x;
    if (idx >= Kp * NP) return;
    int r = idx / NP, c = idx - r * NP;
    const float* ip = in + (size_t)z * inLayerStride;
    __nv_bfloat16* op = out + (size_t)z * outLayerStride;
    float v = (r < K && c < N) ? ip[(size_t)r * N + c] : 0.f;
    __nv_bfloat16 hi = __float2bfloat16(v);
    __nv_bfloat16 lo = __float2bfloat16(v - __bfloat162float(hi));
    op[(size_t)r * NP + c]            = hi;
    op[(size_t)(Kp + r) * NP + c]     = lo;
    op[(size_t)(2 * Kp + r) * NP + c] = hi;
}

struct W6Ptrs { const float* p[6]; };
__global__ __launch_bounds__(256) void splitW6_kernel(
    W6Ptrs w, __nv_bfloat16* __restrict__ out)
{
    int z = blockIdx.z;             // l*6 + t
    int l = z / 6, t = z - l * 6;
    int idx = blockIdx.x * 256 + threadIdx.x;
    if (idx >= KP_IN * D_H) return;
    int r = idx / D_H, c = idx - r * D_H;
    float v = (r < D_IN) ? w.p[t][(size_t)l * D_IN * D_H + (size_t)r * D_H + c] : 0.f;
    __nv_bfloat16 hi = __float2bfloat16(v);
    __nv_bfloat16 lo = __float2bfloat16(v - __bfloat162float(hi));
    __nv_bfloat16* o = out + (size_t)z * K3_IN * D_H;
    o[(size_t)r * D_H + c]                = hi;
    o[(size_t)(KP_IN + r) * D_H + c]      = lo;
    o[(size_t)(2 * KP_IN + r) * D_H + c]  = hi;
}

// ---------------- bf16 tensor-core GEMM (64x64 warp tile, 3-stage) ----------
template <int ACT>  // 0=none, 1=relu, 2=leaky(0.01)
__device__ __forceinline__ void bgemm_body(
    const __nv_bfloat16* __restrict__ A, int lda,
    const __nv_bfloat16* __restrict__ B, int ldb,
    const float* __restrict__ bias, const float* __restrict__ resid, int ldr,
    float* __restrict__ C, int ldc, int M, int N, int Kt,
    int rowBase, int colBase)
{
    extern __shared__ char smraw[];
    __nv_bfloat16 (*As)[BM][APAD] = reinterpret_cast<__nv_bfloat16 (*)[BM][APAD]>(smraw);
    __nv_bfloat16 (*Bs)[BK][BPAD] = reinterpret_cast<__nv_bfloat16 (*)[BK][BPAD]>(smraw + SM_B_OFF);
    float (*BiasT)[BN] = reinterpret_cast<float (*)[BN]>(smraw + SM_BIAS_OFF);

    const int tid = threadIdx.x;
    const int wid = tid >> 5;
    const int wm  = wid >> 1;     // 0..1 -> 64-row band
    const int wn  = wid & 1;      // 0..1 -> 64-col band

    wmma::fragment<wmma::accumulator, 16, 16, 16, float> acc[4][4];
#pragma unroll
    for (int mi = 0; mi < 4; mi++)
#pragma unroll
        for (int ni = 0; ni < 4; ni++) wmma::fill_fragment(acc[mi][ni], 0.f);

    for (int l = tid; l < 16 * BN; l += NTHREADS) {
        int r = l >> 7, c = l & 127;
        int gc = colBase + c;
        BiasT[r][c] = (bias != nullptr && gc < N) ? bias[gc] : 0.f;
    }

    const int nK = Kt / BK;

    // per stage: A 128x32 (512 16B-chunks), B 32x128 (512 chunks); 4 each/thread
    auto loadStage = [&](int st, int k0) {
#pragma unroll
        for (int u = 0; u < 4; u++) {
            int ch = u * NTHREADS + tid;
            int r = ch >> 2, c8 = (ch & 3) * 8;
            int gr = rowBase + r;
            cp_async16(&As[st][r][c8], A + (size_t)gr * lda + k0 + c8, gr < M);
        }
#pragma unroll
        for (int u = 0; u < 4; u++) {
            int ch = u * NTHREADS + tid;
            int r = ch >> 4, c8 = (ch & 15) * 8;
            cp_async16(&Bs[st][r][c8], B + (size_t)(k0 + r) * ldb + colBase + c8, true);
        }
        cp_commit();
    };

    loadStage(0, 0);
    if (nK > 1) loadStage(1, BK);

    for (int kt = 0; kt < nK; kt++) {
        int cur = kt % NSTAGE;
        if (kt + 1 < nK) cp_wait<1>(); else cp_wait<0>();
        __syncthreads();
        if (kt + 2 < nK) loadStage((kt + 2) % NSTAGE, (kt + 2) * BK);

#pragma unroll
        for (int ks = 0; ks < BK; ks += 16) {
            wmma::fragment<wmma::matrix_a, 16, 16, 16, __nv_bfloat16, wmma::row_major> af[4];
            wmma::fragment<wmma::matrix_b, 16, 16, 16, __nv_bfloat16, wmma::row_major> bf[4];
#pragma unroll
            for (int mi = 0; mi < 4; mi++)
                wmma::load_matrix_sync(af[mi], &As[cur][wm * 64 + mi * 16][ks], APAD);
#pragma unroll
            for (int ni = 0; ni < 4; ni++)
                wmma::load_matrix_sync(bf[ni], &Bs[cur][ks][wn * 64 + ni * 16], BPAD);
#pragma unroll
            for (int mi = 0; mi < 4; mi++)
#pragma unroll
                for (int ni = 0; ni < 4; ni++)
                    wmma::mma_sync(acc[mi][ni], af[mi], bf[ni], acc[mi][ni]);
        }
    }
    __syncthreads();

#pragma unroll
    for (int mi = 0; mi < 4; mi++) {
        int grow = rowBase + wm * 64 + mi * 16;
        if (grow >= M) continue;
#pragma unroll
        for (int ni = 0; ni < 4; ni++) {
            int gcol = colBase + wn * 64 + ni * 16;
            wmma::fragment<wmma::accumulator, 16, 16, 16, float> bfr;
            wmma::load_matrix_sync(bfr, &BiasT[0][wn * 64 + ni * 16], BN, wmma::mem_row_major);
            if (resid != nullptr) {
                wmma::fragment<wmma::accumulator, 16, 16, 16, float> rfr;
                wmma::load_matrix_sync(rfr, resid + (size_t)grow * ldr + gcol, ldr,
                                       wmma::mem_row_major);
#pragma unroll
                for (int i = 0; i < acc[mi][ni].num_elements; i++)
                    acc[mi][ni].x[i] += rfr.x[i];
            }
#pragma unroll
            for (int i = 0; i < acc[mi][ni].num_elements; i++) {
                float v = acc[mi][ni].x[i] + bfr.x[i];
                if (ACT == 1) v = fmaxf(v, 0.f);
                if (ACT == 2) v = (v > 0.f) ? v : 0.01f * v;
                acc[mi][ni].x[i] = v;
            }
            wmma::store_matrix_sync(C + (size_t)grow * ldc + gcol, acc[mi][ni], ldc,
                                    wmma::mem_row_major);
        }
    }
}

template <int ACT>
__global__ __launch_bounds__(NTHREADS, 2) void bgemm_kernel(
    const __nv_bfloat16* __restrict__ A, int lda,
    const __nv_bfloat16* __restrict__ B, int ldb,
    const float* bias, const float* resid, int ldr,
    float* C, int ldc, int M, int N, int Kt)
{
    bgemm_body<ACT>(A, lda, B, ldb, bias, resid, ldr, C, ldc, M, N, Kt,
                    blockIdx.x * BM, blockIdx.y * BN);
}

struct X6Args {
    const __nv_bfloat16* B[6];
    const float* bias[6];
    float*       C[6];
};
__global__ __launch_bounds__(NTHREADS, 2) void bgemm_x6_kernel(
    const __nv_bfloat16* __restrict__ A, X6Args p, int M)
{
    int z = blockIdx.x;
    bgemm_body<0>(A, K3_IN, p.B[z], D_H, p.bias[z], nullptr, 0,
                  p.C[z], D_H, M, D_H, K3_IN, blockIdx.y * BM, 0);
}

// ---------------- LayerNorm over 128, warp per row -------------------------
__global__ __launch_bounds__(256) void ln128_kernel(
    const float* __restrict__ in, const float* __restrict__ gamma,
    const float* __restrict__ beta, float* __restrict__ out, int M)
{
    int row = blockIdx.x * 8 + (threadIdx.x >> 5);
    if (row >= M) return;
    int lane = threadIdx.x & 31;
    const float* p = in + (size_t)row * D_H;
    float v0 = p[lane], v1 = p[lane + 32], v2 = p[lane + 64], v3 = p[lane + 96];
    float s = v0 + v1 + v2 + v3;
#pragma unroll
    for (int o = 16; o > 0; o >>= 1) s += __shfl_xor_sync(0xFFFFFFFFu, s, o);
    float mean = s * (1.f / 128.f);
    float d0 = v0 - mean, d1 = v1 - mean, d2 = v2 - mean, d3 = v3 - mean;
    float ss = d0 * d0 + d1 * d1 + d2 * d2 + d3 * d3;
#pragma unroll
    for (int o = 16; o > 0; o >>= 1) ss += __shfl_xor_sync(0xFFFFFFFFu, ss, o);
    float inv = rsqrtf(ss * (1.f / 128.f) + 1e-5f);
    float* q = out + (size_t)row * D_H;
    q[lane]      = d0 * inv * gamma[lane]      + beta[lane];
    q[lane + 32] = d1 * inv * gamma[lane + 32] + beta[lane + 32];
    q[lane + 64] = d2 * inv * gamma[lane + 64] + beta[lane + 64];
    q[lane + 96] = d3 * inv * gamma[lane + 96] + beta[lane + 96];
}

// ---------------- edge kernels (warp per edge; edge_index is int32) --------
__global__ __launch_bounds__(256) void att_dot_kernel(
    const int* __restrict__ ei, const float* __restrict__ q,
    const float* __restrict__ k, float* __restrict__ att, int E)
{
    int e = (blockIdx.x * blockDim.x + threadIdx.x) >> 5;
    if (e >= E) return;
    int lane = threadIdx.x & 31;
    size_t s = (size_t)ei[e];
    size_t d = (size_t)ei[E + e];
    const float* qp = q + d * D_H;
    const float* kp = k + s * D_H;
    float sum = qp[lane] * kp[lane] + qp[lane + 32] * kp[lane + 32] +
                qp[lane + 64] * kp[lane + 64] + qp[lane + 96] * kp[lane + 96];
#pragma unroll
    for (int o = 16; o > 0; o >>= 1) sum += __shfl_xor_sync(0xFFFFFFFFu, sum, o);
    if (lane == 0) att[e] = sum;
}

__global__ __launch_bounds__(256) void reduce_max_p1(
    const float* __restrict__ att, int E, float* __restrict__ part)
{
    __shared__ float sm[256];
    float m = -INFINITY;
    for (int i = blockIdx.x * 256 + threadIdx.x; i < E; i += gridDim.x * 256)
        m = fmaxf(m, att[i]);
    sm[threadIdx.x] = m;
    __syncthreads();
    for (int o = 128; o > 0; o >>= 1) {
        if (threadIdx.x < o) sm[threadIdx.x] = fmaxf(sm[threadIdx.x], sm[threadIdx.x + o]);
        __syncthreads();
    }
    if (threadIdx.x == 0) part[blockIdx.x] = sm[0];
}

__global__ __launch_bounds__(512) void reduce_max_p2(
    const float* __restrict__ part, float* __restrict__ out)
{
    __shared__ float sm[512];
    sm[threadIdx.x] = part[threadIdx.x];
    __syncthreads();
    for (int o = 256; o > 0; o >>= 1) {
        if (threadIdx.x < o) sm[threadIdx.x] = fmaxf(sm[threadIdx.x], sm[threadIdx.x + o]);
        __syncthreads();
    }
    if (threadIdx.x == 0) out[0] = sm[0];
}

__global__ __launch_bounds__(256) void reduce_sum_p1(
    const float* __restrict__ att, const float* __restrict__ maxp,
    int E, float* __restrict__ part)
{
    __shared__ float sm[256];
    float mx = maxp[0];
    float s = 0.f;
    for (int i = blockIdx.x * 256 + threadIdx.x; i < E; i += gridDim.x * 256)
        s += __expf(att[i] - mx);
    sm[threadIdx.x] = s;
    __syncthreads();
    for (int o = 128; o > 0; o >>= 1) {
        if (threadIdx.x < o) sm[threadIdx.x] += sm[threadIdx.x + o];
        __syncthreads();
    }
    if (threadIdx.x == 0) part[blockIdx.x] = sm[0];
}

__global__ __launch_bounds__(512) void reduce_sum_p2(
    const float* __restrict__ part, float* __restrict__ out)
{
    __shared__ float sm[512];
    sm[threadIdx.x] = part[threadIdx.x];
    __syncthreads();
    for (int o = 256; o > 0; o >>= 1) {
        if (threadIdx.x < o) sm[threadIdx.x] += sm[threadIdx.x + o];
        __syncthreads();
    }
    if (threadIdx.x == 0) out[0] = sm[0];
}

__global__ __launch_bounds__(256) void message_kernel(
    const int* __restrict__ ei, const float* __restrict__ ea,
    const float* __restrict__ v, const float* __restrict__ hi,
    const float* __restrict__ hj, const float* __restrict__ att,
    const float* __restrict__ red, float* __restrict__ h, int E)
{
    int e = (blockIdx.x * blockDim.x + threadIdx.x) >> 5;
    if (e >= E) return;
    int lane = threadIdx.x & 31;
    size_t s = (size_t)ei[e];
    size_t d = (size_t)ei[E + e];
    float attn = __expf(att[e] - red[0]) * (1.f / red[1]);
    const float* eap = ea + (size_t)e * D_H;
    const float* vp  = v  + s * D_H;
    const float* hip = hi + s * D_H;
    const float* hjp = hj + d * D_H;
    float* hp = h + d * D_H;
#pragma unroll
    for (int c = 0; c < 4; c++) {
        int dim = lane + c * 32;
        float z = eap[dim] + hip[dim] + hjp[dim];
        float gate = 1.f / (1.f + __expf(-z));
        atomicAdd(&hp[dim], attn * vp[dim] * gate);
    }
}

// ---------------- launch ----------------------------------------------------
static inline int cdiv(int a, int b) { return (a + b - 1) / b; }

extern "C" void kernel_launch(void* const* d_in, const int* in_sizes, int n_in,
                              void* d_out, int out_size)
{
    const float* x    = (const float*)d_in[0];
    const int*   ei   = (const int*)d_in[1];
    const float* ea   = (const float*)d_in[2];
    const float* Wq   = (const float*)d_in[3];
    const float* bq   = (const float*)d_in[4];
    const float* Wk   = (const float*)d_in[5];
    const float* bk   = (const float*)d_in[6];
    const float* Wv   = (const float*)d_in[7];
    const float* bv   = (const float*)d_in[8];
    const float* Wr   = (const float*)d_in[9];
    const float* br   = (const float*)d_in[10];
    const float* Whi  = (const float*)d_in[11];
    const float* Whj  = (const float*)d_in[12];
    const float* g1   = (const float*)d_in[13];
    const float* be1  = (const float*)d_in[14];
    const float* W1   = (const float*)d_in[15];
    const float* bl1  = (const float*)d_in[16];
    const float* W2   = (const float*)d_in[17];
    const float* bl2  = (const float*)d_in[18];
    const float* g2   = (const float*)d_in[19];
    const float* be2  = (const float*)d_in[20];
    const float* Wlin = (const float*)d_in[21];
    const float* blin = (const float*)d_in[22];
    const float* Wlin2= (const float*)d_in[23];
    const float* blin2= (const float*)d_in[24];
    float* out = (float*)d_out;

    float *X, *q, *k, *v, *h, *hi, *hj, *ln, *h2, *ff, *att, *part, *red;
    __nv_bfloat16 *Xs, *lns, *ffs, *W6s, *W1s, *W2s, *Wlins, *Wl2s;
    cudaGetSymbolAddress((void**)&X,   g_X);
    cudaGetSymbolAddress((void**)&q,   g_q);
    cudaGetSymbolAddress((void**)&k,   g_k);
    cudaGetSymbolAddress((void**)&v,   g_v);
    cudaGetSymbolAddress((void**)&h,   g_h);
    cudaGetSymbolAddress((void**)&hi,  g_hi);
    cudaGetSymbolAddress((void**)&hj,  g_hj);
    cudaGetSymbolAddress((void**)&ln,  g_ln);
    cudaGetSymbolAddress((void**)&h2,  g_h2);
    cudaGetSymbolAddress((void**)&ff,  g_ff);
    cudaGetSymbolAddress((void**)&att, g_att);
    cudaGetSymbolAddress((void**)&part,g_part);
    cudaGetSymbolAddress((void**)&red, g_red);
    cudaGetSymbolAddress((void**)&Xs,  g_Xs);
    cudaGetSymbolAddress((void**)&lns, g_lns);
    cudaGetSymbolAddress((void**)&ffs, g_ffs);
    cudaGetSymbolAddress((void**)&W6s, g_W6s);
    cudaGetSymbolAddress((void**)&W1s, g_W1s);
    cudaGetSymbolAddress((void**)&W2s, g_W2s);
    cudaGetSymbolAddress((void**)&Wlins, g_Wlins);
    cudaGetSymbolAddress((void**)&Wl2s,  g_Wl2s);

    cudaFuncSetAttribute(bgemm_kernel<0>, cudaFuncAttributeMaxDynamicSharedMemorySize, SM_TOTAL);
    cudaFuncSetAttribute(bgemm_kernel<1>, cudaFuncAttributeMaxDynamicSharedMemorySize, SM_TOTAL);
    cudaFuncSetAttribute(bgemm_kernel<2>, cudaFuncAttributeMaxDynamicSharedMemorySize, SM_TOTAL);
    cudaFuncSetAttribute(bgemm_x6_kernel, cudaFuncAttributeMaxDynamicSharedMemorySize, SM_TOTAL);

    const int M = NNODE, E = NEDGE;
    const int rowTiles = cdiv(M, BM);
    const int edgeBlocks = (E * 32 + 255) / 256;
    const int lnBlocks = (M + 7) / 8;

    splitA_kernel<<<cdiv(M * KP_IN, 256), 256>>>(x, D_IN, M, D_IN, KP_IN, Xs);
    splitBb_kernel<<<dim3(cdiv(D_H * NP_LIN, 256), 1, 1), 256>>>(
        Wlin, D_H, D_IN, D_H, NP_LIN, 0, 0, Wlins);
    splitBb_kernel<<<dim3(cdiv(KP_IN * D_H, 256), 1, 1), 256>>>(
        Wlin2, D_IN, D_H, KP_IN, D_H, 0, 0, Wl2s);
    W6Ptrs wp; wp.p[0]=Wq; wp.p[1]=Wk; wp.p[2]=Wv; wp.p[3]=Wr; wp.p[4]=Whi; wp.p[5]=Whj;
    splitW6_kernel<<<dim3(cdiv(KP_IN * D_H, 256), 1, 12), 256>>>(wp, W6s);
    splitBb_kernel<<<dim3(cdiv(D_H * D_FF, 256), 1, 2), 256>>>(
        W1, D_H, D_FF, D_H, D_FF, (size_t)D_H * D_FF, (size_t)K3_H * D_FF, W1s);
    splitBb_kernel<<<dim3(cdiv(D_FF * D_H, 256), 1, 2), 256>>>(
        W2, D_FF, D_H, D_FF, D_H, (size_t)D_FF * D_H, (size_t)K3_FF * D_H, W2s);

    for (int i = 0; i < 2; i++) {
        // 1) fused 6-way projection
        X6Args a;
        for (int z = 0; z < 6; z++) a.B[z] = W6s + (size_t)(i * 6 + z) * K3_IN * D_H;
        a.bias[0] = bq + (size_t)i * D_H;  a.C[0] = q;
        a.bias[1] = bk + (size_t)i * D_H;  a.C[1] = k;
        a.bias[2] = bv + (size_t)i * D_H;  a.C[2] = v;
        a.bias[3] = br + (size_t)i * D_H;  a.C[3] = h;
        a.bias[4] = nullptr;               a.C[4] = hi;
        a.bias[5] = nullptr;               a.C[5] = hj;
        bgemm_x6_kernel<<<dim3(6, rowTiles), NTHREADS, SM_TOTAL>>>(Xs, a, M);

        // 2) attention + global softmax stats
        att_dot_kernel<<<edgeBlocks, 256>>>(ei, q, k, att, E);
        reduce_max_p1<<<512, 256>>>(att, E, part);
        reduce_max_p2<<<1, 512>>>(part, red);
        reduce_sum_p1<<<512, 256>>>(att, red, E, part);
        reduce_sum_p2<<<1, 512>>>(part, red + 1);

        // 3) gated messages scatter-added onto h
        message_kernel<<<edgeBlocks, 256>>>(ei, ea, v, hi, hj, att, red, h, E);

        // 4) FF MLP with pre-norm residual
        ln128_kernel<<<lnBlocks, 256>>>(h, g1 + (size_t)i * D_H, be1 + (size_t)i * D_H, ln, M);
        splitA_kernel<<<cdiv(M * D_H, 256), 256>>>(ln, D_H, M, D_H, D_H, lns);
        bgemm_kernel<1><<<dim3(rowTiles, D_FF / BN), NTHREADS, SM_TOTAL>>>(
            lns, K3_H, W1s + (size_t)i * K3_H * D_FF, D_FF, bl1 + (size_t)i * D_FF, nullptr, 0,
            ff, D_FF, M, D_FF, K3_H);
        splitA_kernel<<<cdiv(M * D_FF, 256), 256>>>(ff, D_FF, M, D_FF, D_FF, ffs);
        bgemm_kernel<0><<<dim3(rowTiles, 1), NTHREADS, SM_TOTAL>>>(
            ffs, K3_FF, W2s + (size_t)i * K3_FF * D_H, D_H, bl2 + (size_t)i * D_H, h, D_H,
            h2, D_H, M, D_H, K3_FF);
        ln128_kernel<<<lnBlocks, 256>>>(h2, g2 + (size_t)i * D_H, be2 + (size_t)i * D_H, ln, M);

        // 5) expand back to 1546, then split for next consumer
        splitA_kernel<<<cdiv(M * D_H, 256), 256>>>(ln, D_H, M, D_H, D_H, lns);
        bgemm_kernel<0><<<dim3(rowTiles, NP_LIN / BN), NTHREADS, SM_TOTAL>>>(
            lns, K3_H, Wlins, NP_LIN, blin, nullptr, 0,
            X, XSTRIDE, M, D_IN, K3_H);
        splitA_kernel<<<cdiv(M * KP_IN, 256), 256>>>(X, XSTRIDE, M, D_IN, KP_IN, Xs);
    }

    // final: leaky_relu(X @ Wlin2 + blin2)
    bgemm_kernel<2><<<dim3(rowTiles, 1), NTHREADS, SM_TOTAL>>>(
        Xs, K3_IN, Wl2s, D_H, blin2, nullptr, 0,
        out, D_H, M, D_H, K3_IN);
}